// round 2
// baseline (speedup 1.0000x reference)
#include <cuda_runtime.h>

#define N_POI  100000
#define N_EDGE 50000
#define NNZ    3200000
#define DD     128

// ---------------- scratch (static device memory; no allocations) ----------------
__device__ float g_px   [(size_t)N_POI * DD];
__device__ float g_msg  [(size_t)N_EDGE * DD];
__device__ float g_fused[(size_t)N_EDGE * DD];
__device__ float g_p    [(size_t)N_POI * DD];
__device__ float g_psum [(size_t)N_POI * DD];
__device__ float g_e    [(size_t)N_EDGE * DD];
__device__ float g_esum [(size_t)N_EDGE * DD];
__device__ float g_Wc   [DD * DD];

__device__ int   g_rp_p2e [N_EDGE + 1];
__device__ int   g_cur_p2e[N_EDGE];
__device__ int   g_cols_p2e[NNZ];
__device__ float g_vals_p2e[NNZ];

__device__ int   g_rp_e2p [N_POI + 1];
__device__ int   g_cur_e2p[N_POI];
__device__ int   g_cols_e2p[NNZ];
__device__ float g_vals_e2p[NNZ];

// ---------------- small helpers ----------------
__global__ void fill0_kernel(int* __restrict__ p, int n) {
    for (int i = blockIdx.x * blockDim.x + threadIdx.x; i < n; i += gridDim.x * blockDim.x)
        p[i] = 0;
}

__global__ void hist_kernel(const int* __restrict__ rows, int* __restrict__ counts, int nnz) {
    for (int i = blockIdx.x * blockDim.x + threadIdx.x; i < nnz; i += gridDim.x * blockDim.x)
        atomicAdd(&counts[rows[i]], 1);
}

// Single-block exclusive scan of data[0..n-1]; writes data[n] = total and
// copies the exclusive prefix into cursor[].
__global__ void scan_kernel(int* __restrict__ data, int* __restrict__ cursor, int n) {
    __shared__ int partial[1024];
    int t = threadIdx.x;
    int chunk = (n + 1023) / 1024;
    int b = t * chunk;
    int e = min(n, b + chunk);
    int s = 0;
    for (int i = b; i < e; i++) s += data[i];
    partial[t] = s;
    __syncthreads();
    for (int off = 1; off < 1024; off <<= 1) {
        int v  = partial[t];
        int vo = (t >= off) ? partial[t - off] : 0;
        __syncthreads();
        partial[t] = v + vo;
        __syncthreads();
    }
    int run = (t == 0) ? 0 : partial[t - 1];
    for (int i = b; i < e; i++) {
        int c = data[i];
        data[i] = run;
        cursor[i] = run;
        run += c;
    }
    if (t == 1023) data[n] = partial[1023];
}

__global__ void scatter_kernel(const int* __restrict__ rows, const int* __restrict__ colsIn,
                               const float* __restrict__ valsIn, int* __restrict__ cursor,
                               int* __restrict__ outCols, float* __restrict__ outVals, int nnz) {
    for (int i = blockIdx.x * blockDim.x + threadIdx.x; i < nnz; i += gridDim.x * blockDim.x) {
        int r = rows[i];
        int pos = atomicAdd(&cursor[r], 1);
        outCols[pos] = colsIn[i];
        outVals[pos] = valsIn[i];
    }
}

// Wc[j][m] = sum_k W_fus[j][128+k] * W_edge[k][m]   (fold edge GEMM into fusion GEMM)
__global__ void wc_kernel(const float* __restrict__ Wfus, const float* __restrict__ Wedge,
                          float* __restrict__ Wc) {
    int j = blockIdx.x;
    int m = threadIdx.x;
    float s = 0.f;
#pragma unroll 8
    for (int k = 0; k < DD; k++)
        s += Wfus[j * 256 + 128 + k] * Wedge[k * DD + m];
    Wc[j * DD + m] = s;
}

__global__ void init_kernel(const float4* __restrict__ poi, const float4* __restrict__ edge,
                            float4* __restrict__ p, float4* __restrict__ psum,
                            float4* __restrict__ e, float4* __restrict__ esum) {
    const int n1 = N_POI * 32, n2 = N_EDGE * 32;
    for (int i = blockIdx.x * blockDim.x + threadIdx.x; i < n1 + n2; i += gridDim.x * blockDim.x) {
        if (i < n1) {
            float4 v = poi[i];
            p[i] = v; psum[i] = v;
        } else {
            float4 v = edge[i - n1];
            e[i - n1] = v; esum[i - n1] = v;
        }
    }
}

// e_new = fused + e ; e = e_new ; esum += e_new
__global__ void ew_edge_kernel(const float4* __restrict__ fused, float4* __restrict__ e,
                               float4* __restrict__ esum, int n4) {
    for (int i = blockIdx.x * blockDim.x + threadIdx.x; i < n4; i += gridDim.x * blockDim.x) {
        float4 f = fused[i];
        float4 ev = e[i];
        float4 en = make_float4(f.x + ev.x, f.y + ev.y, f.z + ev.z, f.w + ev.w);
        e[i] = en;
        float4 es = esum[i];
        esum[i] = make_float4(es.x + en.x, es.y + en.y, es.z + en.z, es.w + en.w);
    }
}

__global__ void final_kernel(const float4* __restrict__ psum, const float4* __restrict__ esum,
                             float4* __restrict__ out) {
    const float s = 1.0f / 3.0f;
    const int n1 = N_POI * 32, n2 = N_EDGE * 32;
    for (int i = blockIdx.x * blockDim.x + threadIdx.x; i < n1 + n2; i += gridDim.x * blockDim.x) {
        float4 v = (i < n1) ? psum[i] : esum[i - n1];
        out[i] = make_float4(v.x * s, v.y * s, v.z * s, v.w * s);
    }
}

// ---------------- dense GEMM: out[i,j] = (acc ? out[i,j] : 0) + sum_k M[j*mstride+k] * x[i,k]
// 256 threads, 64 rows/block, W staged transposed in smem, 4x8 register tile/thread.
#define GEMM_ROWS 64
#define MSTRIDE   132

__global__ void gemm_kernel(const float* __restrict__ M, int mstride,
                            const float* __restrict__ x, float* __restrict__ out,
                            int nrows, int accumulate) {
    extern __shared__ float sh[];
    float* Ms = sh;                    // [128][MSTRIDE]  Ms[k*MSTRIDE + j] = M[j][k]
    float* xs = sh + DD * MSTRIDE;     // [64][MSTRIDE]   xs[r*MSTRIDE + k]
    int tid = threadIdx.x;
    int row0 = blockIdx.x * GEMM_ROWS;

    for (int idx = tid; idx < DD * DD; idx += 256) {
        int j = idx >> 7, k = idx & 127;
        Ms[k * MSTRIDE + j] = M[j * mstride + k];
    }
    const float4* x4 = (const float4*)x;
    for (int idx = tid; idx < GEMM_ROWS * 32; idx += 256) {
        int r = idx >> 5, k4 = idx & 31;
        int gr = row0 + r;
        float4 v = (gr < nrows) ? x4[(size_t)gr * 32 + k4] : make_float4(0.f, 0.f, 0.f, 0.f);
        *(float4*)&xs[r * MSTRIDE + k4 * 4] = v;
    }
    __syncthreads();

    int tx = tid & 15, ty = tid >> 4;   // tx: 8-col group, ty: 4-row group
    float acc[4][8];
#pragma unroll
    for (int i = 0; i < 4; i++)
#pragma unroll
        for (int j = 0; j < 8; j++) acc[i][j] = 0.f;

#pragma unroll 4
    for (int k = 0; k < DD; ++k) {
        float b[8];
        *(float4*)&b[0] = *(const float4*)&Ms[k * MSTRIDE + tx * 8];
        *(float4*)&b[4] = *(const float4*)&Ms[k * MSTRIDE + tx * 8 + 4];
        float a[4];
#pragma unroll
        for (int i = 0; i < 4; i++) a[i] = xs[(ty * 4 + i) * MSTRIDE + k];
#pragma unroll
        for (int i = 0; i < 4; i++)
#pragma unroll
            for (int j = 0; j < 8; j++)
                acc[i][j] += a[i] * b[j];
    }

#pragma unroll
    for (int i = 0; i < 4; i++) {
        int gr = row0 + ty * 4 + i;
        if (gr < nrows) {
            float4* op = (float4*)&out[(size_t)gr * DD + tx * 8];
            float4 o0 = make_float4(acc[i][0], acc[i][1], acc[i][2], acc[i][3]);
            float4 o1 = make_float4(acc[i][4], acc[i][5], acc[i][6], acc[i][7]);
            if (accumulate) {
                float4 c0 = op[0], c1 = op[1];
                o0.x += c0.x; o0.y += c0.y; o0.z += c0.z; o0.w += c0.w;
                o1.x += c1.x; o1.y += c1.y; o1.z += c1.z; o1.w += c1.w;
            }
            op[0] = o0;
            op[1] = o1;
        }
    }
}

// ---------------- CSR SpMM: one warp per output row, lane owns 4 columns ----------------
__device__ __forceinline__ void spmm_row_acc(const int* __restrict__ cols,
                                             const float* __restrict__ vals,
                                             const float4* __restrict__ x4,
                                             int s, int e, int lane,
                                             float& ax, float& ay, float& az, float& aw) {
    int j = s;
    for (; j + 4 <= e; j += 4) {
        int c0 = cols[j], c1 = cols[j + 1], c2 = cols[j + 2], c3 = cols[j + 3];
        float v0 = vals[j], v1 = vals[j + 1], v2 = vals[j + 2], v3 = vals[j + 3];
        float4 r0 = x4[(size_t)c0 * 32 + lane];
        float4 r1 = x4[(size_t)c1 * 32 + lane];
        float4 r2 = x4[(size_t)c2 * 32 + lane];
        float4 r3 = x4[(size_t)c3 * 32 + lane];
        ax += v0 * r0.x; ay += v0 * r0.y; az += v0 * r0.z; aw += v0 * r0.w;
        ax += v1 * r1.x; ay += v1 * r1.y; az += v1 * r1.z; aw += v1 * r1.w;
        ax += v2 * r2.x; ay += v2 * r2.y; az += v2 * r2.z; aw += v2 * r2.w;
        ax += v3 * r3.x; ay += v3 * r3.y; az += v3 * r3.z; aw += v3 * r3.w;
    }
    for (; j < e; ++j) {
        int c = cols[j];
        float v = vals[j];
        float4 r = x4[(size_t)c * 32 + lane];
        ax += v * r.x; ay += v * r.y; az += v * r.z; aw += v * r.w;
    }
}

__global__ void spmm_kernel(const int* __restrict__ rp, const int* __restrict__ cols,
                            const float* __restrict__ vals, const float* __restrict__ x,
                            float* __restrict__ out, int nrows) {
    int warp = (int)((blockIdx.x * (unsigned)blockDim.x + threadIdx.x) >> 5);
    if (warp >= nrows) return;
    int lane = threadIdx.x & 31;
    int s = rp[warp], e = rp[warp + 1];
    float ax = 0.f, ay = 0.f, az = 0.f, aw = 0.f;
    spmm_row_acc(cols, vals, (const float4*)x, s, e, lane, ax, ay, az, aw);
    ((float4*)out)[(size_t)warp * 32 + lane] = make_float4(ax, ay, az, aw);
}

// SpMM e2p with fused residual: p = p + acc ; psum += p_new
__global__ void spmm_update_kernel(const int* __restrict__ rp, const int* __restrict__ cols,
                                   const float* __restrict__ vals, const float* __restrict__ x,
                                   float* __restrict__ p, float* __restrict__ psum, int nrows) {
    int warp = (int)((blockIdx.x * (unsigned)blockDim.x + threadIdx.x) >> 5);
    if (warp >= nrows) return;
    int lane = threadIdx.x & 31;
    int s = rp[warp], e = rp[warp + 1];
    float ax = 0.f, ay = 0.f, az = 0.f, aw = 0.f;
    spmm_row_acc(cols, vals, (const float4*)x, s, e, lane, ax, ay, az, aw);
    size_t o = (size_t)warp * 32 + lane;
    float4 pv = ((float4*)p)[o];
    float4 pn = make_float4(pv.x + ax, pv.y + ay, pv.z + az, pv.w + aw);
    ((float4*)p)[o] = pn;
    float4 ps = ((float4*)psum)[o];
    ((float4*)psum)[o] = make_float4(ps.x + pn.x, ps.y + pn.y, ps.z + pn.z, ps.w + pn.w);
}

// ---------------- host ----------------
static void* sym_addr(const void* s) {
    void* p = nullptr;
    cudaGetSymbolAddress(&p, s);
    return p;
}

extern "C" void kernel_launch(void* const* d_in, const int* in_sizes, int n_in,
                              void* d_out, int out_size) {
    const float* poi    = (const float*)d_in[0];
    const float* edge   = (const float*)d_in[1];
    const float* Wpoi   = (const float*)d_in[2];
    const float* Wedge  = (const float*)d_in[3];
    const float* Wfus   = (const float*)d_in[4];
    const int*   p2e_r  = (const int*)d_in[5];
    const int*   p2e_c  = (const int*)d_in[6];
    const float* p2e_v  = (const float*)d_in[7];
    const int*   e2p_r  = (const int*)d_in[8];
    const int*   e2p_c  = (const int*)d_in[9];
    const float* e2p_v  = (const float*)d_in[10];
    float* out = (float*)d_out;

    float* px    = (float*)sym_addr(g_px);
    float* msg   = (float*)sym_addr(g_msg);
    float* fused = (float*)sym_addr(g_fused);
    float* p     = (float*)sym_addr(g_p);
    float* psum  = (float*)sym_addr(g_psum);
    float* e     = (float*)sym_addr(g_e);
    float* esum  = (float*)sym_addr(g_esum);
    float* Wc    = (float*)sym_addr(g_Wc);
    int*   rpA   = (int*)sym_addr(g_rp_p2e);
    int*   curA  = (int*)sym_addr(g_cur_p2e);
    int*   colsA = (int*)sym_addr(g_cols_p2e);
    float* valsA = (float*)sym_addr(g_vals_p2e);
    int*   rpB   = (int*)sym_addr(g_rp_e2p);
    int*   curB  = (int*)sym_addr(g_cur_e2p);
    int*   colsB = (int*)sym_addr(g_cols_e2p);
    float* valsB = (float*)sym_addr(g_vals_e2p);

    size_t smem = (size_t)(DD * MSTRIDE + GEMM_ROWS * MSTRIDE) * sizeof(float);
    cudaFuncSetAttribute(gemm_kernel, cudaFuncAttributeMaxDynamicSharedMemorySize, (int)smem);

    // --- build CSR for both COO matrices (counting sort; runs inside the graph) ---
    fill0_kernel<<<256, 256>>>(rpA, N_EDGE + 1);
    fill0_kernel<<<256, 256>>>(rpB, N_POI + 1);
    hist_kernel<<<(NNZ + 255) / 256, 256>>>(p2e_r, rpA, NNZ);
    hist_kernel<<<(NNZ + 255) / 256, 256>>>(e2p_r, rpB, NNZ);
    scan_kernel<<<1, 1024>>>(rpA, curA, N_EDGE);
    scan_kernel<<<1, 1024>>>(rpB, curB, N_POI);
    scatter_kernel<<<(NNZ + 255) / 256, 256>>>(p2e_r, p2e_c, p2e_v, curA, colsA, valsA, NNZ);
    scatter_kernel<<<(NNZ + 255) / 256, 256>>>(e2p_r, e2p_c, e2p_v, curB, colsB, valsB, NNZ);

    // --- folded weight + state init ---
    wc_kernel<<<DD, DD>>>(Wfus, Wedge, Wc);
    init_kernel<<<4096, 256>>>((const float4*)poi, (const float4*)edge,
                               (float4*)p, (float4*)psum, (float4*)e, (float4*)esum);

    // --- 2 layers ---
    for (int layer = 0; layer < 2; ++layer) {
        gemm_kernel<<<(N_POI + GEMM_ROWS - 1) / GEMM_ROWS, 256, smem>>>(Wpoi, 128, p, px, N_POI, 0);
        spmm_kernel<<<(N_EDGE + 7) / 8, 256>>>(rpA, colsA, valsA, px, msg, N_EDGE);
        gemm_kernel<<<(N_EDGE + GEMM_ROWS - 1) / GEMM_ROWS, 256, smem>>>(Wfus, 256, msg, fused, N_EDGE, 0);
        gemm_kernel<<<(N_EDGE + GEMM_ROWS - 1) / GEMM_ROWS, 256, smem>>>(Wc, 128, e, fused, N_EDGE, 1);
        ew_edge_kernel<<<2048, 256>>>((const float4*)fused, (float4*)e, (float4*)esum, N_EDGE * 32);
        spmm_update_kernel<<<(N_POI + 7) / 8, 256>>>(rpB, colsB, valsB, fused, p, psum, N_POI);
    }

    final_kernel<<<4096, 256>>>((const float4*)psum, (const float4*)esum, (float4*)out);
}

// round 3
// speedup vs baseline: 1.4797x; 1.4797x over previous
#include <cuda_runtime.h>

#define N_POI  100000
#define N_EDGE 50000
#define NNZ    3200000
#define DD     128

struct Pair { int c; float v; };

// ---------------- static scratch ----------------
__device__ float g_msg  [(size_t)N_EDGE * DD];
__device__ float g_fused[(size_t)N_EDGE * DD];
__device__ float g_p    [(size_t)N_POI * DD];
__device__ float g_psum [(size_t)N_POI * DD];
__device__ float g_e    [(size_t)N_EDGE * DD];
__device__ float g_esum [(size_t)N_EDGE * DD];
__device__ float g_Wcomb[DD * 256];            // [j][0:128]=Wf1@Wpoi, [j][128:256]=Wf2@Wedge

__device__ int  g_rpA [N_EDGE + 1];
__device__ int  g_curA[N_EDGE];
__device__ Pair g_pairsA[NNZ];
__device__ int  g_rpB [N_POI + 1];
__device__ int  g_curB[N_POI];
__device__ Pair g_pairsB[NNZ];

// ---------------- CSR build (counting sort, runs every replay) ----------------
__global__ void clear_kernel(int* __restrict__ a, int na, int* __restrict__ b, int nb) {
    for (int i = blockIdx.x * blockDim.x + threadIdx.x; i < na + nb; i += gridDim.x * blockDim.x) {
        if (i < na) a[i] = 0; else b[i - na] = 0;
    }
}

__global__ void hist2_kernel(const int* __restrict__ rA, const int* __restrict__ rB,
                             int* __restrict__ cA, int* __restrict__ cB) {
    const int total = 2 * NNZ;
    for (int i = blockIdx.x * blockDim.x + threadIdx.x; i < total; i += gridDim.x * blockDim.x) {
        if (i < NNZ) atomicAdd(&cA[rA[i]], 1);
        else         atomicAdd(&cB[rB[i - NNZ]], 1);
    }
}

// gridDim.x == 2 : block 0 scans A, block 1 scans B. 1024 threads.
__global__ void scan2_kernel(int* __restrict__ dA, int* __restrict__ curA, int nA,
                             int* __restrict__ dB, int* __restrict__ curB, int nB) {
    __shared__ int partial[1024];
    int* data   = (blockIdx.x == 0) ? dA : dB;
    int* cursor = (blockIdx.x == 0) ? curA : curB;
    int  n      = (blockIdx.x == 0) ? nA : nB;
    int t = threadIdx.x;
    int chunk = (n + 1023) / 1024;
    int b = t * chunk;
    int e = min(n, b + chunk);
    int s = 0;
    for (int i = b; i < e; i++) s += data[i];
    partial[t] = s;
    __syncthreads();
    for (int off = 1; off < 1024; off <<= 1) {
        int v  = partial[t];
        int vo = (t >= off) ? partial[t - off] : 0;
        __syncthreads();
        partial[t] = v + vo;
        __syncthreads();
    }
    int run = (t == 0) ? 0 : partial[t - 1];
    for (int i = b; i < e; i++) {
        int c = data[i];
        data[i] = run;
        cursor[i] = run;
        run += c;
    }
    if (t == 1023) data[n] = partial[1023];
}

__global__ void scatter2_kernel(const int* __restrict__ rA, const int* __restrict__ cAi,
                                const float* __restrict__ vAi, int* __restrict__ curA,
                                Pair* __restrict__ pA,
                                const int* __restrict__ rB, const int* __restrict__ cBi,
                                const float* __restrict__ vBi, int* __restrict__ curB,
                                Pair* __restrict__ pB) {
    const int total = 2 * NNZ;
    for (int i = blockIdx.x * blockDim.x + threadIdx.x; i < total; i += gridDim.x * blockDim.x) {
        if (i < NNZ) {
            int r = rA[i];
            int pos = atomicAdd(&curA[r], 1);
            Pair pr; pr.c = cAi[i]; pr.v = vAi[i];
            pA[pos] = pr;
        } else {
            int k = i - NNZ;
            int r = rB[k];
            int pos = atomicAdd(&curB[r], 1);
            Pair pr; pr.c = cBi[k]; pr.v = vBi[k];
            pB[pos] = pr;
        }
    }
}

// ---------------- weight folding ----------------
// Wcomb[j][t] (t<128)  = sum_m Wfus[j][m]     * Wpoi[m][t]
// Wcomb[j][t] (t>=128) = sum_k Wfus[j][128+k] * Wedge[k][t-128]
__global__ void wfold_kernel(const float* __restrict__ Wfus, const float* __restrict__ Wpoi,
                             const float* __restrict__ Wedge, float* __restrict__ Wcomb) {
    __shared__ float row[256];
    int j = blockIdx.x;
    int t = threadIdx.x;
    row[t] = Wfus[j * 256 + t];
    __syncthreads();
    float s = 0.f;
    if (t < 128) {
#pragma unroll 8
        for (int m = 0; m < 128; m++) s += row[m] * Wpoi[m * 128 + t];
    } else {
        int tt = t - 128;
#pragma unroll 8
        for (int k = 0; k < 128; k++) s += row[128 + k] * Wedge[k * 128 + tt];
    }
    Wcomb[j * 256 + t] = s;
}

__global__ void init_kernel(const float4* __restrict__ poi, const float4* __restrict__ edge,
                            float4* __restrict__ p, float4* __restrict__ psum,
                            float4* __restrict__ e, float4* __restrict__ esum) {
    const int n1 = N_POI * 32, n2 = N_EDGE * 32;
    for (int i = blockIdx.x * blockDim.x + threadIdx.x; i < n1 + n2; i += gridDim.x * blockDim.x) {
        if (i < n1) {
            float4 v = poi[i];
            p[i] = v; psum[i] = v;
        } else {
            float4 v = edge[i - n1];
            e[i - n1] = v; esum[i - n1] = v;
        }
    }
}

// ---------------- CSR SpMM core: one warp per row, lane owns 4 cols ----------------
__device__ __forceinline__ void spmm_row_acc(const Pair* __restrict__ prs,
                                             const float4* __restrict__ x4,
                                             int s, int e, int lane,
                                             float& ax, float& ay, float& az, float& aw) {
    int j = s;
    for (; j + 4 <= e; j += 4) {
        Pair p0 = prs[j], p1 = prs[j + 1], p2 = prs[j + 2], p3 = prs[j + 3];
        float4 r0 = x4[(size_t)p0.c * 32 + lane];
        float4 r1 = x4[(size_t)p1.c * 32 + lane];
        float4 r2 = x4[(size_t)p2.c * 32 + lane];
        float4 r3 = x4[(size_t)p3.c * 32 + lane];
        ax += p0.v * r0.x; ay += p0.v * r0.y; az += p0.v * r0.z; aw += p0.v * r0.w;
        ax += p1.v * r1.x; ay += p1.v * r1.y; az += p1.v * r1.z; aw += p1.v * r1.w;
        ax += p2.v * r2.x; ay += p2.v * r2.y; az += p2.v * r2.z; aw += p2.v * r2.w;
        ax += p3.v * r3.x; ay += p3.v * r3.y; az += p3.v * r3.z; aw += p3.v * r3.w;
    }
    for (; j < e; ++j) {
        Pair pp = prs[j];
        float4 r = x4[(size_t)pp.c * 32 + lane];
        ax += pp.v * r.x; ay += pp.v * r.y; az += pp.v * r.z; aw += pp.v * r.w;
    }
}

// msg = spmm_p2e(p)
__global__ void __launch_bounds__(256) spmmA_kernel(const int* __restrict__ rp,
                                                    const Pair* __restrict__ prs,
                                                    const float* __restrict__ x,
                                                    float* __restrict__ out) {
    int warp = (int)((blockIdx.x * (unsigned)blockDim.x + threadIdx.x) >> 5);
    if (warp >= N_EDGE) return;
    int lane = threadIdx.x & 31;
    int s = rp[warp], e = rp[warp + 1];
    float ax = 0.f, ay = 0.f, az = 0.f, aw = 0.f;
    spmm_row_acc(prs, (const float4*)x, s, e, lane, ax, ay, az, aw);
    ((float4*)out)[(size_t)warp * 32 + lane] = make_float4(ax, ay, az, aw);
}

// prop = spmm_e2p(fused); p_new = p + prop;
// LAST==0: p=p_new, psum+=p_new.  LAST==1: out = (psum + p_new)/3.
template <int LAST>
__global__ void __launch_bounds__(256) spmmB_kernel(const int* __restrict__ rp,
                                                    const Pair* __restrict__ prs,
                                                    const float* __restrict__ x,
                                                    float* __restrict__ p,
                                                    float* __restrict__ psum,
                                                    float* __restrict__ out) {
    int warp = (int)((blockIdx.x * (unsigned)blockDim.x + threadIdx.x) >> 5);
    if (warp >= N_POI) return;
    int lane = threadIdx.x & 31;
    int s = rp[warp], e = rp[warp + 1];
    float ax = 0.f, ay = 0.f, az = 0.f, aw = 0.f;
    spmm_row_acc(prs, (const float4*)x, s, e, lane, ax, ay, az, aw);
    size_t o = (size_t)warp * 32 + lane;
    float4 pv = ((const float4*)p)[o];
    float4 pn = make_float4(pv.x + ax, pv.y + ay, pv.z + az, pv.w + aw);
    if (LAST == 0) {
        ((float4*)p)[o] = pn;
        float4 ps = ((const float4*)psum)[o];
        ((float4*)psum)[o] = make_float4(ps.x + pn.x, ps.y + pn.y, ps.z + pn.z, ps.w + pn.w);
    } else {
        const float sc = 1.0f / 3.0f;
        float4 ps = ((const float4*)psum)[o];
        ((float4*)out)[o] = make_float4((ps.x + pn.x) * sc, (ps.y + pn.y) * sc,
                                        (ps.z + pn.z) * sc, (ps.w + pn.w) * sc);
    }
}

// ---------------- combined edge GEMM + residual epilogue ----------------
// fused[i][j] = sum_{k<128} msg[i][k]*Wcomb[j][k] + sum_{k<128} e[i][k]*Wcomb[j][128+k]
// LAST==0: e_new = e + fused; e = e_new; esum += e_new; store fused.
// LAST==1: store fused; out_edge = (esum + e + fused)/3.
#define GEMM_ROWS 64
#define MSTR      132

template <int LAST>
__global__ void __launch_bounds__(256, 2) gemm2_kernel(const float* __restrict__ Wcomb,
                                                       const float* __restrict__ msg,
                                                       const float* __restrict__ e,
                                                       float* __restrict__ fused,
                                                       float* __restrict__ esum,
                                                       float* __restrict__ out_edge) {
    extern __shared__ float sh[];
    float* Ws = sh;                    // [128 k][MSTR]  Ws[k*MSTR + j]
    float* xs = sh + DD * MSTR;        // [64 r][MSTR]
    int tid = threadIdx.x;
    int row0 = blockIdx.x * GEMM_ROWS;
    int tx = tid & 15, ty = tid >> 4;

    float acc[4][8];
#pragma unroll
    for (int i = 0; i < 4; i++)
#pragma unroll
        for (int j = 0; j < 8; j++) acc[i][j] = 0.f;

#pragma unroll
    for (int phase = 0; phase < 2; phase++) {
        const float* src = phase ? e : msg;
        int koff = phase * 128;
        if (phase) __syncthreads();   // protect previous tiles before restage
        for (int idx = tid; idx < DD * DD; idx += 256) {
            int j = idx >> 7, k = idx & 127;
            Ws[k * MSTR + j] = Wcomb[j * 256 + koff + k];
        }
        const float4* s4 = (const float4*)src;
        for (int idx = tid; idx < GEMM_ROWS * 32; idx += 256) {
            int r = idx >> 5, k4 = idx & 31;
            int gr = row0 + r;
            float4 v = (gr < N_EDGE) ? s4[(size_t)gr * 32 + k4] : make_float4(0.f, 0.f, 0.f, 0.f);
            *(float4*)&xs[r * MSTR + k4 * 4] = v;
        }
        __syncthreads();

#pragma unroll 4
        for (int k = 0; k < DD; ++k) {
            float b[8];
            *(float4*)&b[0] = *(const float4*)&Ws[k * MSTR + tx * 8];
            *(float4*)&b[4] = *(const float4*)&Ws[k * MSTR + tx * 8 + 4];
            float a[4];
#pragma unroll
            for (int i = 0; i < 4; i++) a[i] = xs[(ty * 4 + i) * MSTR + k];
#pragma unroll
            for (int i = 0; i < 4; i++)
#pragma unroll
                for (int j = 0; j < 8; j++)
                    acc[i][j] += a[i] * b[j];
        }
    }

    // epilogue: xs currently holds e rows for this tile
#pragma unroll
    for (int i = 0; i < 4; i++) {
        int r = ty * 4 + i;
        int gr = row0 + r;
        if (gr >= N_EDGE) continue;
        size_t base = (size_t)gr * DD + tx * 8;
        float f[8];
#pragma unroll
        for (int j = 0; j < 8; j++) f[j] = acc[i][j];
        // store fused
        *(float4*)&fused[base]     = make_float4(f[0], f[1], f[2], f[3]);
        *(float4*)&fused[base + 4] = make_float4(f[4], f[5], f[6], f[7]);
        float eo[8];
#pragma unroll
        for (int j = 0; j < 8; j++) eo[j] = xs[r * MSTR + tx * 8 + j];
        if (LAST == 0) {
            float en[8];
#pragma unroll
            for (int j = 0; j < 8; j++) en[j] = eo[j] + f[j];
            *(float4*)&((float*)e)[base]     = make_float4(en[0], en[1], en[2], en[3]);
            *(float4*)&((float*)e)[base + 4] = make_float4(en[4], en[5], en[6], en[7]);
            float4 s0 = *(const float4*)&esum[base];
            float4 s1 = *(const float4*)&esum[base + 4];
            *(float4*)&esum[base]     = make_float4(s0.x + en[0], s0.y + en[1], s0.z + en[2], s0.w + en[3]);
            *(float4*)&esum[base + 4] = make_float4(s1.x + en[4], s1.y + en[5], s1.z + en[6], s1.w + en[7]);
        } else {
            const float sc = 1.0f / 3.0f;
            float4 s0 = *(const float4*)&esum[base];
            float4 s1 = *(const float4*)&esum[base + 4];
            *(float4*)&out_edge[base]     = make_float4((s0.x + eo[0] + f[0]) * sc, (s0.y + eo[1] + f[1]) * sc,
                                                        (s0.z + eo[2] + f[2]) * sc, (s0.w + eo[3] + f[3]) * sc);
            *(float4*)&out_edge[base + 4] = make_float4((s1.x + eo[4] + f[4]) * sc, (s1.y + eo[5] + f[5]) * sc,
                                                        (s1.z + eo[6] + f[6]) * sc, (s1.w + eo[7] + f[7]) * sc);
        }
    }
}

// ---------------- host ----------------
static void* sym_addr(const void* s) {
    void* p = nullptr;
    cudaGetSymbolAddress(&p, s);
    return p;
}

extern "C" void kernel_launch(void* const* d_in, const int* in_sizes, int n_in,
                              void* d_out, int out_size) {
    const float* poi    = (const float*)d_in[0];
    const float* edge   = (const float*)d_in[1];
    const float* Wpoi   = (const float*)d_in[2];
    const float* Wedge  = (const float*)d_in[3];
    const float* Wfus   = (const float*)d_in[4];
    const int*   p2e_r  = (const int*)d_in[5];
    const int*   p2e_c  = (const int*)d_in[6];
    const float* p2e_v  = (const float*)d_in[7];
    const int*   e2p_r  = (const int*)d_in[8];
    const int*   e2p_c  = (const int*)d_in[9];
    const float* e2p_v  = (const float*)d_in[10];
    float* out = (float*)d_out;
    float* out_edge = out + (size_t)N_POI * DD;

    float* msg   = (float*)sym_addr(g_msg);
    float* fused = (float*)sym_addr(g_fused);
    float* p     = (float*)sym_addr(g_p);
    float* psum  = (float*)sym_addr(g_psum);
    float* e     = (float*)sym_addr(g_e);
    float* esum  = (float*)sym_addr(g_esum);
    float* Wcomb = (float*)sym_addr(g_Wcomb);
    int*   rpA   = (int*)sym_addr(g_rpA);
    int*   curA  = (int*)sym_addr(g_curA);
    Pair*  prsA  = (Pair*)sym_addr(g_pairsA);
    int*   rpB   = (int*)sym_addr(g_rpB);
    int*   curB  = (int*)sym_addr(g_curB);
    Pair*  prsB  = (Pair*)sym_addr(g_pairsB);

    size_t smem = (size_t)(DD * MSTR + GEMM_ROWS * MSTR) * sizeof(float);
    cudaFuncSetAttribute(gemm2_kernel<0>, cudaFuncAttributeMaxDynamicSharedMemorySize, (int)smem);
    cudaFuncSetAttribute(gemm2_kernel<1>, cudaFuncAttributeMaxDynamicSharedMemorySize, (int)smem);

    // CSR build (every replay; inputs constant, result order may vary -> sums identical within fp tol)
    clear_kernel<<<128, 256>>>(rpA, N_EDGE + 1, rpB, N_POI + 1);
    hist2_kernel<<<4096, 256>>>(p2e_r, e2p_r, rpA, rpB);
    scan2_kernel<<<2, 1024>>>(rpA, curA, N_EDGE, rpB, curB, N_POI);
    scatter2_kernel<<<4096, 256>>>(p2e_r, p2e_c, p2e_v, curA, prsA,
                                   e2p_r, e2p_c, e2p_v, curB, prsB);

    wfold_kernel<<<DD, 256>>>(Wfus, Wpoi, Wedge, Wcomb);
    init_kernel<<<4096, 256>>>((const float4*)poi, (const float4*)edge,
                               (float4*)p, (float4*)psum, (float4*)e, (float4*)esum);

    const int gemmBlocks = (N_EDGE + GEMM_ROWS - 1) / GEMM_ROWS;

    // layer 1
    spmmA_kernel<<<(N_EDGE + 7) / 8, 256>>>(rpA, prsA, p, msg);
    gemm2_kernel<0><<<gemmBlocks, 256, smem>>>(Wcomb, msg, e, fused, esum, nullptr);
    spmmB_kernel<0><<<(N_POI + 7) / 8, 256>>>(rpB, prsB, fused, p, psum, nullptr);

    // layer 2 (last): write outputs directly
    spmmA_kernel<<<(N_EDGE + 7) / 8, 256>>>(rpA, prsA, p, msg);
    gemm2_kernel<1><<<gemmBlocks, 256, smem>>>(Wcomb, msg, e, fused, esum, out_edge);
    spmmB_kernel<1><<<(N_POI + 7) / 8, 256>>>(rpB, prsB, fused, p, psum, out);
}

// round 4
// speedup vs baseline: 1.7849x; 1.2063x over previous
#include <cuda_runtime.h>
#include <cuda_fp16.h>

#define N_POI  100000
#define N_EDGE 50000
#define NNZ    3200000
#define DD     128

struct Pair { int c; float v; };

// ---------------- static scratch ----------------
__device__ float g_msg [(size_t)N_EDGE * DD];
__device__ float g_p1  [(size_t)N_POI * DD];
__device__ float g_e1  [(size_t)N_EDGE * DD];
__device__ float g_esum[(size_t)N_EDGE * DD];
__device__ __half g_ph    [(size_t)N_POI * DD];   // fp16 gather source for spmmA (p0 then p1)
__device__ __half g_fusedh[(size_t)N_EDGE * DD];  // fp16 gather source for spmmB
__device__ float g_Wcomb[DD * 256];

__device__ int  g_rpA [N_EDGE + 1];
__device__ int  g_curA[N_EDGE];
__device__ Pair g_pairsA[NNZ];
__device__ int  g_rpB [N_POI + 1];
__device__ int  g_curB[N_POI];
__device__ Pair g_pairsB[NNZ];

// ---------------- CSR build ----------------
__global__ void clear_kernel(int* __restrict__ a, int na, int* __restrict__ b, int nb) {
    for (int i = blockIdx.x * blockDim.x + threadIdx.x; i < na + nb; i += gridDim.x * blockDim.x) {
        if (i < na) a[i] = 0; else b[i - na] = 0;
    }
}

__global__ void __launch_bounds__(256) hist2_kernel(const int* __restrict__ rA, const int* __restrict__ rB,
                                                    int* __restrict__ cA, int* __restrict__ cB) {
    const int total = 2 * NNZ;
    const int S = gridDim.x * blockDim.x;
    int base = blockIdx.x * blockDim.x + threadIdx.x;
    for (; base < total; base += 4 * S) {
        int r[4]; bool m[4]; bool isA[4];
#pragma unroll
        for (int j = 0; j < 4; j++) {
            int i = base + j * S;
            m[j] = i < total;
            isA[j] = i < NNZ;
            if (m[j]) r[j] = isA[j] ? rA[i] : rB[i - NNZ];
        }
#pragma unroll
        for (int j = 0; j < 4; j++) {
            if (m[j]) {
                if (isA[j]) atomicAdd(&cA[r[j]], 1);
                else        atomicAdd(&cB[r[j]], 1);
            }
        }
    }
}

// gridDim.x == 2: block 0 scans A, block 1 scans B
__global__ void scan2_kernel(int* __restrict__ dA, int* __restrict__ curA, int nA,
                             int* __restrict__ dB, int* __restrict__ curB, int nB) {
    __shared__ int partial[1024];
    int* data   = (blockIdx.x == 0) ? dA : dB;
    int* cursor = (blockIdx.x == 0) ? curA : curB;
    int  n      = (blockIdx.x == 0) ? nA : nB;
    int t = threadIdx.x;
    int chunk = (n + 1023) / 1024;
    int b = t * chunk;
    int e = min(n, b + chunk);
    int s = 0;
    for (int i = b; i < e; i++) s += data[i];
    partial[t] = s;
    __syncthreads();
    for (int off = 1; off < 1024; off <<= 1) {
        int v  = partial[t];
        int vo = (t >= off) ? partial[t - off] : 0;
        __syncthreads();
        partial[t] = v + vo;
        __syncthreads();
    }
    int run = (t == 0) ? 0 : partial[t - 1];
    for (int i = b; i < e; i++) {
        int c = data[i];
        data[i] = run;
        cursor[i] = run;
        run += c;
    }
    if (t == 1023) data[n] = partial[1023];
}

__global__ void __launch_bounds__(256) scatter2_kernel(const int* __restrict__ rA, const int* __restrict__ cAi,
                                                       const float* __restrict__ vAi, int* __restrict__ curA,
                                                       Pair* __restrict__ pA,
                                                       const int* __restrict__ rB, const int* __restrict__ cBi,
                                                       const float* __restrict__ vBi, int* __restrict__ curB,
                                                       Pair* __restrict__ pB) {
    const int total = 2 * NNZ;
    const int S = gridDim.x * blockDim.x;
    int base = blockIdx.x * blockDim.x + threadIdx.x;
    for (; base < total; base += 4 * S) {
        int r[4], c[4]; float v[4]; bool m[4], isA[4];
#pragma unroll
        for (int j = 0; j < 4; j++) {
            int i = base + j * S;
            m[j] = i < total;
            isA[j] = i < NNZ;
            if (m[j]) {
                if (isA[j]) { r[j] = rA[i]; c[j] = cAi[i]; v[j] = vAi[i]; }
                else        { int k = i - NNZ; r[j] = rB[k]; c[j] = cBi[k]; v[j] = vBi[k]; }
            }
        }
#pragma unroll
        for (int j = 0; j < 4; j++) {
            if (m[j]) {
                Pair pr; pr.c = c[j]; pr.v = v[j];
                if (isA[j]) { int pos = atomicAdd(&curA[r[j]], 1); pA[pos] = pr; }
                else        { int pos = atomicAdd(&curB[r[j]], 1); pB[pos] = pr; }
            }
        }
    }
}

// ---------------- weight folding ----------------
__global__ void wfold_kernel(const float* __restrict__ Wfus, const float* __restrict__ Wpoi,
                             const float* __restrict__ Wedge, float* __restrict__ Wcomb) {
    __shared__ float row[256];
    int j = blockIdx.x;
    int t = threadIdx.x;
    row[t] = Wfus[j * 256 + t];
    __syncthreads();
    float s = 0.f;
    if (t < 128) {
#pragma unroll 8
        for (int m = 0; m < 128; m++) s += row[m] * Wpoi[m * 128 + t];
    } else {
        int tt = t - 128;
#pragma unroll 8
        for (int k = 0; k < 128; k++) s += row[128 + k] * Wedge[k * 128 + tt];
    }
    Wcomb[j * 256 + t] = s;
}

// poi fp32 -> fp16 (gather source for layer-1 spmmA)
__global__ void conv_kernel(const float4* __restrict__ x, uint2* __restrict__ xh, int n4) {
    for (int i = blockIdx.x * blockDim.x + threadIdx.x; i < n4; i += gridDim.x * blockDim.x) {
        float4 v = x[i];
        __half2 h0 = __floats2half2_rn(v.x, v.y);
        __half2 h1 = __floats2half2_rn(v.z, v.w);
        uint2 u;
        u.x = *(unsigned*)&h0;
        u.y = *(unsigned*)&h1;
        xh[i] = u;
    }
}

// ---------------- SpMM core: one warp per row, lane owns 4 cols, fp16 gather ----------------
__device__ __forceinline__ void spmm_row_acc_h(const Pair* __restrict__ prs,
                                               const uint2* __restrict__ xh,
                                               int s, int e, int lane,
                                               float& ax, float& ay, float& az, float& aw) {
    int j = s;
    for (; j + 4 <= e; j += 4) {
        Pair p0 = prs[j], p1 = prs[j + 1], p2 = prs[j + 2], p3 = prs[j + 3];
        uint2 g0 = xh[(size_t)p0.c * 32 + lane];
        uint2 g1 = xh[(size_t)p1.c * 32 + lane];
        uint2 g2 = xh[(size_t)p2.c * 32 + lane];
        uint2 g3 = xh[(size_t)p3.c * 32 + lane];
#pragma unroll
        for (int q = 0; q < 4; q++) {
            uint2 g = q == 0 ? g0 : q == 1 ? g1 : q == 2 ? g2 : g3;
            float v = q == 0 ? p0.v : q == 1 ? p1.v : q == 2 ? p2.v : p3.v;
            float2 f01 = __half22float2(*(__half2*)&g.x);
            float2 f23 = __half22float2(*(__half2*)&g.y);
            ax += v * f01.x; ay += v * f01.y; az += v * f23.x; aw += v * f23.y;
        }
    }
    for (; j < e; ++j) {
        Pair pp = prs[j];
        uint2 g = xh[(size_t)pp.c * 32 + lane];
        float2 f01 = __half22float2(*(__half2*)&g.x);
        float2 f23 = __half22float2(*(__half2*)&g.y);
        ax += pp.v * f01.x; ay += pp.v * f01.y; az += pp.v * f23.x; aw += pp.v * f23.y;
    }
}

// msg = spmm_p2e(ph)
__global__ void __launch_bounds__(256) spmmA_kernel(const int* __restrict__ rp,
                                                    const Pair* __restrict__ prs,
                                                    const __half* __restrict__ xh,
                                                    float* __restrict__ out) {
    int warp = (int)((blockIdx.x * (unsigned)blockDim.x + threadIdx.x) >> 5);
    if (warp >= N_EDGE) return;
    int lane = threadIdx.x & 31;
    int s = rp[warp], e = rp[warp + 1];
    float ax = 0.f, ay = 0.f, az = 0.f, aw = 0.f;
    spmm_row_acc_h(prs, (const uint2*)xh, s, e, lane, ax, ay, az, aw);
    ((float4*)out)[(size_t)warp * 32 + lane] = make_float4(ax, ay, az, aw);
}

// LAST==0: p1 = poi + acc; store p1 (fp32) + ph (fp16)
// LAST==1: out = (poi + 2*p1 + acc)/3
template <int LAST>
__global__ void __launch_bounds__(256) spmmB_kernel(const int* __restrict__ rp,
                                                    const Pair* __restrict__ prs,
                                                    const __half* __restrict__ xh,
                                                    const float* __restrict__ poi,
                                                    float* __restrict__ p1,
                                                    __half* __restrict__ ph,
                                                    float* __restrict__ out) {
    int warp = (int)((blockIdx.x * (unsigned)blockDim.x + threadIdx.x) >> 5);
    if (warp >= N_POI) return;
    int lane = threadIdx.x & 31;
    int s = rp[warp], e = rp[warp + 1];
    float ax = 0.f, ay = 0.f, az = 0.f, aw = 0.f;
    spmm_row_acc_h(prs, (const uint2*)xh, s, e, lane, ax, ay, az, aw);
    size_t o = (size_t)warp * 32 + lane;
    float4 p0 = ((const float4*)poi)[o];
    if (LAST == 0) {
        float4 pn = make_float4(p0.x + ax, p0.y + ay, p0.z + az, p0.w + aw);
        ((float4*)p1)[o] = pn;
        __half2 h0 = __floats2half2_rn(pn.x, pn.y);
        __half2 h1 = __floats2half2_rn(pn.z, pn.w);
        uint2 u;
        u.x = *(unsigned*)&h0;
        u.y = *(unsigned*)&h1;
        ((uint2*)ph)[o] = u;
    } else {
        const float sc = 1.0f / 3.0f;
        float4 pv = ((const float4*)p1)[o];
        ((float4*)out)[o] = make_float4((p0.x + 2.f * pv.x + ax) * sc,
                                        (p0.y + 2.f * pv.y + ay) * sc,
                                        (p0.z + 2.f * pv.z + az) * sc,
                                        (p0.w + 2.f * pv.w + aw) * sc);
    }
}

// ---------------- edge GEMM + residual epilogue ----------------
// f[i][j] = sum_k msg[i][k]*Wcomb[j][k] + sum_k e_in[i][k]*Wcomb[j][128+k]
// LAST==0: e_out = e_in + f; esum = 2*e_in + f; fused_h = fp16(f)
// LAST==1: out_edge = (esum + e_in + f)/3; fused_h = fp16(f)
#define GR   128
#define MSTR 132

template <int LAST>
__global__ void __launch_bounds__(256, 1) gemm2_kernel(const float* __restrict__ Wcomb,
                                                       const float* __restrict__ msg,
                                                       const float* __restrict__ e_in,
                                                       __half* __restrict__ fused_h,
                                                       float* __restrict__ e_out,
                                                       float* __restrict__ esum,
                                                       float* __restrict__ out_edge) {
    extern __shared__ float sh[];
    float* Ws = sh;                 // [128 k][MSTR] transposed weights
    float* xs = sh + DD * MSTR;     // [128 r][MSTR]
    int tid = threadIdx.x;
    int row0 = blockIdx.x * GR;
    int tx = tid & 15, ty = tid >> 4;

    float acc[8][8];
#pragma unroll
    for (int i = 0; i < 8; i++)
#pragma unroll
        for (int j = 0; j < 8; j++) acc[i][j] = 0.f;

#pragma unroll
    for (int phase = 0; phase < 2; phase++) {
        const float* src = phase ? e_in : msg;
        int koff = phase * 128;
        if (phase) __syncthreads();
        for (int idx = tid; idx < DD * DD; idx += 256) {
            int j = idx >> 7, k = idx & 127;
            Ws[k * MSTR + j] = Wcomb[j * 256 + koff + k];
        }
        const float4* s4 = (const float4*)src;
        for (int idx = tid; idx < GR * 32; idx += 256) {
            int r = idx >> 5, k4 = idx & 31;
            int gr = row0 + r;
            float4 v = (gr < N_EDGE) ? s4[(size_t)gr * 32 + k4] : make_float4(0.f, 0.f, 0.f, 0.f);
            *(float4*)&xs[r * MSTR + k4 * 4] = v;
        }
        __syncthreads();

#pragma unroll 4
        for (int k = 0; k < DD; ++k) {
            float b[8];
            *(float4*)&b[0] = *(const float4*)&Ws[k * MSTR + tx * 8];
            *(float4*)&b[4] = *(const float4*)&Ws[k * MSTR + tx * 8 + 4];
            float a[8];
#pragma unroll
            for (int i = 0; i < 8; i++) a[i] = xs[(ty * 8 + i) * MSTR + k];
#pragma unroll
            for (int i = 0; i < 8; i++)
#pragma unroll
                for (int j = 0; j < 8; j++)
                    acc[i][j] += a[i] * b[j];
        }
    }

    // epilogue: xs holds e_in rows for this tile
#pragma unroll
    for (int i = 0; i < 8; i++) {
        int r = ty * 8 + i;
        int gr = row0 + r;
        if (gr >= N_EDGE) continue;
        size_t base = (size_t)gr * DD + tx * 8;
        float f[8];
#pragma unroll
        for (int j = 0; j < 8; j++) f[j] = acc[i][j];
        // store fused as fp16
        __half2 h[4];
#pragma unroll
        for (int j = 0; j < 4; j++) h[j] = __floats2half2_rn(f[2 * j], f[2 * j + 1]);
        uint4 hv;
        hv.x = *(unsigned*)&h[0]; hv.y = *(unsigned*)&h[1];
        hv.z = *(unsigned*)&h[2]; hv.w = *(unsigned*)&h[3];
        ((uint4*)fused_h)[(size_t)gr * 16 + tx] = hv;

        float eo[8];
#pragma unroll
        for (int j = 0; j < 8; j++) eo[j] = xs[r * MSTR + tx * 8 + j];
        if (LAST == 0) {
            float en[8];
#pragma unroll
            for (int j = 0; j < 8; j++) en[j] = eo[j] + f[j];
            *(float4*)&e_out[base]     = make_float4(en[0], en[1], en[2], en[3]);
            *(float4*)&e_out[base + 4] = make_float4(en[4], en[5], en[6], en[7]);
            *(float4*)&esum[base]     = make_float4(eo[0] + en[0], eo[1] + en[1], eo[2] + en[2], eo[3] + en[3]);
            *(float4*)&esum[base + 4] = make_float4(eo[4] + en[4], eo[5] + en[5], eo[6] + en[6], eo[7] + en[7]);
        } else {
            const float sc = 1.0f / 3.0f;
            float4 s0 = *(const float4*)&esum[base];
            float4 s1 = *(const float4*)&esum[base + 4];
            *(float4*)&out_edge[base]     = make_float4((s0.x + eo[0] + f[0]) * sc, (s0.y + eo[1] + f[1]) * sc,
                                                        (s0.z + eo[2] + f[2]) * sc, (s0.w + eo[3] + f[3]) * sc);
            *(float4*)&out_edge[base + 4] = make_float4((s1.x + eo[4] + f[4]) * sc, (s1.y + eo[5] + f[5]) * sc,
                                                        (s1.z + eo[6] + f[6]) * sc, (s1.w + eo[7] + f[7]) * sc);
        }
    }
}

// ---------------- host ----------------
static void* sym_addr(const void* s) {
    void* p = nullptr;
    cudaGetSymbolAddress(&p, s);
    return p;
}

extern "C" void kernel_launch(void* const* d_in, const int* in_sizes, int n_in,
                              void* d_out, int out_size) {
    const float* poi    = (const float*)d_in[0];
    const float* edge   = (const float*)d_in[1];
    const float* Wpoi   = (const float*)d_in[2];
    const float* Wedge  = (const float*)d_in[3];
    const float* Wfus   = (const float*)d_in[4];
    const int*   p2e_r  = (const int*)d_in[5];
    const int*   p2e_c  = (const int*)d_in[6];
    const float* p2e_v  = (const float*)d_in[7];
    const int*   e2p_r  = (const int*)d_in[8];
    const int*   e2p_c  = (const int*)d_in[9];
    const float* e2p_v  = (const float*)d_in[10];
    float* out = (float*)d_out;
    float* out_edge = out + (size_t)N_POI * DD;

    float*  msg    = (float*)sym_addr(g_msg);
    float*  p1     = (float*)sym_addr(g_p1);
    float*  e1     = (float*)sym_addr(g_e1);
    float*  esum   = (float*)sym_addr(g_esum);
    __half* ph     = (__half*)sym_addr(g_ph);
    __half* fusedh = (__half*)sym_addr(g_fusedh);
    float*  Wcomb  = (float*)sym_addr(g_Wcomb);
    int*    rpA    = (int*)sym_addr(g_rpA);
    int*    curA   = (int*)sym_addr(g_curA);
    Pair*   prsA   = (Pair*)sym_addr(g_pairsA);
    int*    rpB    = (int*)sym_addr(g_rpB);
    int*    curB   = (int*)sym_addr(g_curB);
    Pair*   prsB   = (Pair*)sym_addr(g_pairsB);

    size_t smem = (size_t)(DD * MSTR + GR * MSTR) * sizeof(float);
    cudaFuncSetAttribute(gemm2_kernel<0>, cudaFuncAttributeMaxDynamicSharedMemorySize, (int)smem);
    cudaFuncSetAttribute(gemm2_kernel<1>, cudaFuncAttributeMaxDynamicSharedMemorySize, (int)smem);

    const int buildGrid = (2 * NNZ + 4 * 256 - 1) / (4 * 256);

    // CSR build
    clear_kernel<<<128, 256>>>(rpA, N_EDGE + 1, rpB, N_POI + 1);
    hist2_kernel<<<buildGrid, 256>>>(p2e_r, e2p_r, rpA, rpB);
    scan2_kernel<<<2, 1024>>>(rpA, curA, N_EDGE, rpB, curB, N_POI);
    scatter2_kernel<<<buildGrid, 256>>>(p2e_r, p2e_c, p2e_v, curA, prsA,
                                        e2p_r, e2p_c, e2p_v, curB, prsB);

    wfold_kernel<<<DD, 256>>>(Wfus, Wpoi, Wedge, Wcomb);
    conv_kernel<<<2048, 256>>>((const float4*)poi, (uint2*)ph, N_POI * 32);

    const int gemmBlocks = (N_EDGE + GR - 1) / GR;

    // layer 1
    spmmA_kernel<<<(N_EDGE + 7) / 8, 256>>>(rpA, prsA, ph, msg);
    gemm2_kernel<0><<<gemmBlocks, 256, smem>>>(Wcomb, msg, edge, fusedh, e1, esum, nullptr);
    spmmB_kernel<0><<<(N_POI + 7) / 8, 256>>>(rpB, prsB, fusedh, poi, p1, ph, nullptr);

    // layer 2 (last)
    spmmA_kernel<<<(N_EDGE + 7) / 8, 256>>>(rpA, prsA, ph, msg);
    gemm2_kernel<1><<<gemmBlocks, 256, smem>>>(Wcomb, msg, e1, fusedh, nullptr, esum, out_edge);
    spmmB_kernel<1><<<(N_POI + 7) / 8, 256>>>(rpB, prsB, fusedh, poi, p1, nullptr, out);
}

// round 7
// speedup vs baseline: 2.0034x; 1.1224x over previous
#include <cuda_runtime.h>
#include <cuda_fp16.h>
#include <mma.h>

using namespace nvcuda;

#define N_POI  100000
#define N_EDGE 50000
#define NNZ    3200000
#define DD     128
#define SUB    8

struct Pair { int c; float v; };

// ---------------- static scratch ----------------
__device__ float g_msg [(size_t)N_EDGE * DD];
__device__ float g_p1  [(size_t)N_POI * DD];
__device__ float g_e1  [(size_t)N_EDGE * DD];
__device__ float g_esum[(size_t)N_EDGE * DD];
__device__ __half g_ph    [(size_t)N_POI * DD];
__device__ __half g_fusedh[(size_t)N_EDGE * DD];
__device__ float g_Wcomb[DD * 256];

__device__ int  g_cntA[SUB * N_EDGE];
__device__ int  g_cntB[SUB * N_POI];
__device__ int  g_rpA [N_EDGE + 1];
__device__ int  g_rpB [N_POI + 1];
__device__ int  g_curA[SUB * N_EDGE];
__device__ int  g_curB[SUB * N_POI];
__device__ Pair g_pairsA[NNZ];
__device__ Pair g_pairsB[NNZ];

// ---------------- CSR build ----------------
__global__ void clear_kernel(int* __restrict__ a, int na, int* __restrict__ b, int nb) {
    for (int i = blockIdx.x * blockDim.x + threadIdx.x; i < na + nb; i += gridDim.x * blockDim.x) {
        if (i < na) a[i] = 0; else b[i - na] = 0;
    }
}

__global__ void __launch_bounds__(256) hist2_kernel(const int* __restrict__ rA, const int* __restrict__ rB,
                                                    int* __restrict__ cA, int* __restrict__ cB) {
    const int total = 2 * NNZ;
    const int S = gridDim.x * blockDim.x;
    int base = blockIdx.x * blockDim.x + threadIdx.x;
    int sub = base & (SUB - 1);
    for (; base < total; base += 4 * S) {
        int r[4]; bool m[4]; bool isA[4];
#pragma unroll
        for (int j = 0; j < 4; j++) {
            int i = base + j * S;
            m[j] = i < total;
            isA[j] = i < NNZ;
            if (m[j]) r[j] = isA[j] ? rA[i] : rB[i - NNZ];
        }
#pragma unroll
        for (int j = 0; j < 4; j++) {
            if (m[j]) {
                if (isA[j]) atomicAdd(&cA[r[j] * SUB + sub], 1);
                else        atomicAdd(&cB[r[j] * SUB + sub], 1);
            }
        }
    }
}

// row totals -> rp arrays (pre-scan)
__global__ void rowsum_kernel(const int4* __restrict__ cntA, const int4* __restrict__ cntB,
                              int* __restrict__ rpA, int* __restrict__ rpB) {
    const int total = N_EDGE + N_POI;
    for (int r = blockIdx.x * blockDim.x + threadIdx.x; r < total; r += gridDim.x * blockDim.x) {
        if (r < N_EDGE) {
            int4 a = cntA[r * 2], b = cntA[r * 2 + 1];
            rpA[r] = a.x + a.y + a.z + a.w + b.x + b.y + b.z + b.w;
        } else {
            int rr = r - N_EDGE;
            int4 a = cntB[rr * 2], b = cntB[rr * 2 + 1];
            rpB[rr] = a.x + a.y + a.z + a.w + b.x + b.y + b.z + b.w;
        }
    }
}

// gridDim.x == 2: block 0 scans A, block 1 scans B. In-place exclusive scan + total.
__global__ void scan2_kernel(int* __restrict__ dA, int nA, int* __restrict__ dB, int nB) {
    __shared__ int partial[1024];
    int* data = (blockIdx.x == 0) ? dA : dB;
    int  n    = (blockIdx.x == 0) ? nA : nB;
    int t = threadIdx.x;
    int chunk = (n + 1023) / 1024;
    int b = t * chunk;
    int e = min(n, b + chunk);
    int s = 0;
    for (int i = b; i < e; i++) s += data[i];
    partial[t] = s;
    __syncthreads();
    for (int off = 1; off < 1024; off <<= 1) {
        int v  = partial[t];
        int vo = (t >= off) ? partial[t - off] : 0;
        __syncthreads();
        partial[t] = v + vo;
        __syncthreads();
    }
    int run = (t == 0) ? 0 : partial[t - 1];
    for (int i = b; i < e; i++) {
        int c = data[i];
        data[i] = run;
        run += c;
    }
    if (t == 1023) data[n] = partial[1023];
}

// cursors: cur[r][s] = rp[r] + prefix_{s'<s} cnt[r][s']
__global__ void cursor_kernel(const int* __restrict__ rpA, const int4* __restrict__ cntA, int4* __restrict__ curA,
                              const int* __restrict__ rpB, const int4* __restrict__ cntB, int4* __restrict__ curB) {
    const int total = N_EDGE + N_POI;
    for (int r = blockIdx.x * blockDim.x + threadIdx.x; r < total; r += gridDim.x * blockDim.x) {
        const int4* cnt; int4* cur; int base;
        int rr;
        if (r < N_EDGE) { rr = r; cnt = cntA; cur = curA; base = rpA[r]; }
        else            { rr = r - N_EDGE; cnt = cntB; cur = curB; base = rpB[rr]; }
        int4 a = cnt[rr * 2], b = cnt[rr * 2 + 1];
        int4 oa, ob;
        oa.x = base;
        oa.y = oa.x + a.x;
        oa.z = oa.y + a.y;
        oa.w = oa.z + a.z;
        ob.x = oa.w + a.w;
        ob.y = ob.x + b.x;
        ob.z = ob.y + b.y;
        ob.w = ob.z + b.z;
        cur[rr * 2] = oa;
        cur[rr * 2 + 1] = ob;
    }
}

__global__ void __launch_bounds__(256) scatter2_kernel(const int* __restrict__ rA, const int* __restrict__ cAi,
                                                       const float* __restrict__ vAi, int* __restrict__ curA,
                                                       Pair* __restrict__ pA,
                                                       const int* __restrict__ rB, const int* __restrict__ cBi,
                                                       const float* __restrict__ vBi, int* __restrict__ curB,
                                                       Pair* __restrict__ pB) {
    const int total = 2 * NNZ;
    const int S = gridDim.x * blockDim.x;
    int base = blockIdx.x * blockDim.x + threadIdx.x;
    int sub = base & (SUB - 1);
    for (; base < total; base += 4 * S) {
        int r[4], c[4]; float v[4]; bool m[4], isA[4];
#pragma unroll
        for (int j = 0; j < 4; j++) {
            int i = base + j * S;
            m[j] = i < total;
            isA[j] = i < NNZ;
            if (m[j]) {
                if (isA[j]) { r[j] = rA[i]; c[j] = cAi[i]; v[j] = vAi[i]; }
                else        { int k = i - NNZ; r[j] = rB[k]; c[j] = cBi[k]; v[j] = vBi[k]; }
            }
        }
#pragma unroll
        for (int j = 0; j < 4; j++) {
            if (m[j]) {
                Pair pr; pr.c = c[j]; pr.v = v[j];
                if (isA[j]) { int pos = atomicAdd(&curA[r[j] * SUB + sub], 1); pA[pos] = pr; }
                else        { int pos = atomicAdd(&curB[r[j] * SUB + sub], 1); pB[pos] = pr; }
            }
        }
    }
}

// ---------------- weight folding ----------------
__global__ void wfold_kernel(const float* __restrict__ Wfus, const float* __restrict__ Wpoi,
                             const float* __restrict__ Wedge, float* __restrict__ Wcomb) {
    __shared__ float row[256];
    int j = blockIdx.x;
    int t = threadIdx.x;
    row[t] = Wfus[j * 256 + t];
    __syncthreads();
    float s = 0.f;
    if (t < 128) {
#pragma unroll 8
        for (int m = 0; m < 128; m++) s += row[m] * Wpoi[m * 128 + t];
    } else {
        int tt = t - 128;
#pragma unroll 8
        for (int k = 0; k < 128; k++) s += row[128 + k] * Wedge[k * 128 + tt];
    }
    Wcomb[j * 256 + t] = s;
}

__global__ void conv_kernel(const float4* __restrict__ x, uint2* __restrict__ xh, int n4) {
    for (int i = blockIdx.x * blockDim.x + threadIdx.x; i < n4; i += gridDim.x * blockDim.x) {
        float4 v = x[i];
        __half2 h0 = __floats2half2_rn(v.x, v.y);
        __half2 h1 = __floats2half2_rn(v.z, v.w);
        uint2 u;
        u.x = *(unsigned*)&h0;
        u.y = *(unsigned*)&h1;
        xh[i] = u;
    }
}

// ---------------- SpMM core ----------------
__device__ __forceinline__ void spmm_row_acc_h(const Pair* __restrict__ prs,
                                               const uint2* __restrict__ xh,
                                               int s, int e, int lane,
                                               float& ax, float& ay, float& az, float& aw) {
    int j = s;
    for (; j + 4 <= e; j += 4) {
        Pair p0 = prs[j], p1 = prs[j + 1], p2 = prs[j + 2], p3 = prs[j + 3];
        uint2 g0 = xh[(size_t)p0.c * 32 + lane];
        uint2 g1 = xh[(size_t)p1.c * 32 + lane];
        uint2 g2 = xh[(size_t)p2.c * 32 + lane];
        uint2 g3 = xh[(size_t)p3.c * 32 + lane];
#pragma unroll
        for (int q = 0; q < 4; q++) {
            uint2 g = q == 0 ? g0 : q == 1 ? g1 : q == 2 ? g2 : g3;
            float v = q == 0 ? p0.v : q == 1 ? p1.v : q == 2 ? p2.v : p3.v;
            float2 f01 = __half22float2(*(__half2*)&g.x);
            float2 f23 = __half22float2(*(__half2*)&g.y);
            ax += v * f01.x; ay += v * f01.y; az += v * f23.x; aw += v * f23.y;
        }
    }
    for (; j < e; ++j) {
        Pair pp = prs[j];
        uint2 g = xh[(size_t)pp.c * 32 + lane];
        float2 f01 = __half22float2(*(__half2*)&g.x);
        float2 f23 = __half22float2(*(__half2*)&g.y);
        ax += pp.v * f01.x; ay += pp.v * f01.y; az += pp.v * f23.x; aw += pp.v * f23.y;
    }
}

__global__ void __launch_bounds__(256) spmmA_kernel(const int* __restrict__ rp,
                                                    const Pair* __restrict__ prs,
                                                    const __half* __restrict__ xh,
                                                    float* __restrict__ out) {
    int warp = (int)((blockIdx.x * (unsigned)blockDim.x + threadIdx.x) >> 5);
    if (warp >= N_EDGE) return;
    int lane = threadIdx.x & 31;
    int s = rp[warp], e = rp[warp + 1];
    float ax = 0.f, ay = 0.f, az = 0.f, aw = 0.f;
    spmm_row_acc_h(prs, (const uint2*)xh, s, e, lane, ax, ay, az, aw);
    ((float4*)out)[(size_t)warp * 32 + lane] = make_float4(ax, ay, az, aw);
}

template <int LAST>
__global__ void __launch_bounds__(256) spmmB_kernel(const int* __restrict__ rp,
                                                    const Pair* __restrict__ prs,
                                                    const __half* __restrict__ xh,
                                                    const float* __restrict__ poi,
                                                    float* __restrict__ p1,
                                                    __half* __restrict__ ph,
                                                    float* __restrict__ out) {
    int warp = (int)((blockIdx.x * (unsigned)blockDim.x + threadIdx.x) >> 5);
    if (warp >= N_POI) return;
    int lane = threadIdx.x & 31;
    int s = rp[warp], e = rp[warp + 1];
    float ax = 0.f, ay = 0.f, az = 0.f, aw = 0.f;
    spmm_row_acc_h(prs, (const uint2*)xh, s, e, lane, ax, ay, az, aw);
    size_t o = (size_t)warp * 32 + lane;
    float4 p0 = ((const float4*)poi)[o];
    if (LAST == 0) {
        float4 pn = make_float4(p0.x + ax, p0.y + ay, p0.z + az, p0.w + aw);
        ((float4*)p1)[o] = pn;
        __half2 h0 = __floats2half2_rn(pn.x, pn.y);
        __half2 h1 = __floats2half2_rn(pn.z, pn.w);
        uint2 u;
        u.x = *(unsigned*)&h0;
        u.y = *(unsigned*)&h1;
        ((uint2*)ph)[o] = u;
    } else {
        const float sc = 1.0f / 3.0f;
        float4 pv = ((const float4*)p1)[o];
        ((float4*)out)[o] = make_float4((p0.x + 2.f * pv.x + ax) * sc,
                                        (p0.y + 2.f * pv.y + ay) * sc,
                                        (p0.z + 2.f * pv.z + az) * sc,
                                        (p0.w + 2.f * pv.w + aw) * sc);
    }
}

// ---------------- edge GEMM (tf32 wmma) + residual epilogue ----------------
#define GR   128
#define MSTR 132

template <int LAST>
__global__ void __launch_bounds__(256, 1) gemm2_kernel(const float* __restrict__ Wcomb,
                                                       const float* __restrict__ msg,
                                                       const float* __restrict__ e_in,
                                                       __half* __restrict__ fused_h,
                                                       float* __restrict__ e_out,
                                                       float* __restrict__ esum,
                                                       float* __restrict__ out_edge) {
    extern __shared__ float sh[];
    float* Ws = sh;                 // [128 k][MSTR] transposed weights; reused as C buffer
    float* xs = sh + DD * MSTR;     // [128 r][MSTR] input rows
    int tid = threadIdx.x;
    int wid = tid >> 5;
    int row0 = blockIdx.x * GR;
    int warp_m = wid & 3;           // 4 row groups of 32
    int warp_n = wid >> 2;          // 2 col groups of 64

    wmma::fragment<wmma::accumulator, 16, 16, 8, float> acc[2][4];
#pragma unroll
    for (int m = 0; m < 2; m++)
#pragma unroll
        for (int n = 0; n < 4; n++) wmma::fill_fragment(acc[m][n], 0.f);

#pragma unroll
    for (int phase = 0; phase < 2; phase++) {
        const float* src = phase ? e_in : msg;
        int koff = phase * 128;
        if (phase) __syncthreads();
        for (int idx = tid; idx < DD * DD; idx += 256) {
            int j = idx >> 7, k = idx & 127;
            Ws[k * MSTR + j] = Wcomb[j * 256 + koff + k];
        }
        const float4* s4 = (const float4*)src;
        for (int idx = tid; idx < GR * 32; idx += 256) {
            int r = idx >> 5, k4 = idx & 31;
            int gr = row0 + r;
            float4 v = (gr < N_EDGE) ? s4[(size_t)gr * 32 + k4] : make_float4(0.f, 0.f, 0.f, 0.f);
            *(float4*)&xs[r * MSTR + k4 * 4] = v;
        }
        __syncthreads();

        for (int k0 = 0; k0 < DD; k0 += 8) {
            wmma::fragment<wmma::matrix_a, 16, 16, 8, wmma::precision::tf32, wmma::row_major> a[2];
#pragma unroll
            for (int m = 0; m < 2; m++) {
                wmma::load_matrix_sync(a[m], &xs[(warp_m * 32 + m * 16) * MSTR + k0], MSTR);
#pragma unroll
                for (int t = 0; t < a[m].num_elements; t++)
                    a[m].x[t] = wmma::__float_to_tf32(a[m].x[t]);
            }
#pragma unroll
            for (int n = 0; n < 4; n++) {
                wmma::fragment<wmma::matrix_b, 16, 16, 8, wmma::precision::tf32, wmma::row_major> b;
                wmma::load_matrix_sync(b, &Ws[k0 * MSTR + warp_n * 64 + n * 16], MSTR);
#pragma unroll
                for (int t = 0; t < b.num_elements; t++)
                    b.x[t] = wmma::__float_to_tf32(b.x[t]);
#pragma unroll
                for (int m = 0; m < 2; m++)
                    wmma::mma_sync(acc[m][n], a[m], b, acc[m][n]);
            }
        }
    }

    __syncthreads();   // everyone done reading Ws
#pragma unroll
    for (int m = 0; m < 2; m++)
#pragma unroll
        for (int n = 0; n < 4; n++)
            wmma::store_matrix_sync(&Ws[(warp_m * 32 + m * 16) * MSTR + warp_n * 64 + n * 16],
                                    acc[m][n], MSTR, wmma::mem_row_major);
    __syncthreads();

    // epilogue: Ws holds f (128x128), xs holds e_in rows
    int tx = tid & 15, ty = tid >> 4;
#pragma unroll
    for (int i = 0; i < 8; i++) {
        int r = ty * 8 + i;
        int gr = row0 + r;
        if (gr >= N_EDGE) continue;
        size_t base = (size_t)gr * DD + tx * 8;
        float f[8];
#pragma unroll
        for (int j = 0; j < 8; j++) f[j] = Ws[r * MSTR + tx * 8 + j];
        __half2 h[4];
#pragma unroll
        for (int j = 0; j < 4; j++) h[j] = __floats2half2_rn(f[2 * j], f[2 * j + 1]);
        uint4 hv;
        hv.x = *(unsigned*)&h[0]; hv.y = *(unsigned*)&h[1];
        hv.z = *(unsigned*)&h[2]; hv.w = *(unsigned*)&h[3];
        ((uint4*)fused_h)[(size_t)gr * 16 + tx] = hv;

        float eo[8];
#pragma unroll
        for (int j = 0; j < 8; j++) eo[j] = xs[r * MSTR + tx * 8 + j];
        if (LAST == 0) {
            float en[8];
#pragma unroll
            for (int j = 0; j < 8; j++) en[j] = eo[j] + f[j];
            *(float4*)&e_out[base]     = make_float4(en[0], en[1], en[2], en[3]);
            *(float4*)&e_out[base + 4] = make_float4(en[4], en[5], en[6], en[7]);
            *(float4*)&esum[base]     = make_float4(eo[0] + en[0], eo[1] + en[1], eo[2] + en[2], eo[3] + en[3]);
            *(float4*)&esum[base + 4] = make_float4(eo[4] + en[4], eo[5] + en[5], eo[6] + en[6], eo[7] + en[7]);
        } else {
            const float sc = 1.0f / 3.0f;
            float4 s0 = *(const float4*)&esum[base];
            float4 s1 = *(const float4*)&esum[base + 4];
            *(float4*)&out_edge[base]     = make_float4((s0.x + eo[0] + f[0]) * sc, (s0.y + eo[1] + f[1]) * sc,
                                                        (s0.z + eo[2] + f[2]) * sc, (s0.w + eo[3] + f[3]) * sc);
            *(float4*)&out_edge[base + 4] = make_float4((s1.x + eo[4] + f[4]) * sc, (s1.y + eo[5] + f[5]) * sc,
                                                        (s1.z + eo[6] + f[6]) * sc, (s1.w + eo[7] + f[7]) * sc);
        }
    }
}

// ---------------- host ----------------
static void* sym_addr(const void* s) {
    void* p = nullptr;
    cudaGetSymbolAddress(&p, s);
    return p;
}

extern "C" void kernel_launch(void* const* d_in, const int* in_sizes, int n_in,
                              void* d_out, int out_size) {
    const float* poi    = (const float*)d_in[0];
    const float* edge   = (const float*)d_in[1];
    const float* Wpoi   = (const float*)d_in[2];
    const float* Wedge  = (const float*)d_in[3];
    const float* Wfus   = (const float*)d_in[4];
    const int*   p2e_r  = (const int*)d_in[5];
    const int*   p2e_c  = (const int*)d_in[6];
    const float* p2e_v  = (const float*)d_in[7];
    const int*   e2p_r  = (const int*)d_in[8];
    const int*   e2p_c  = (const int*)d_in[9];
    const float* e2p_v  = (const float*)d_in[10];
    float* out = (float*)d_out;
    float* out_edge = out + (size_t)N_POI * DD;

    float*  msg    = (float*)sym_addr(g_msg);
    float*  p1     = (float*)sym_addr(g_p1);
    float*  e1     = (float*)sym_addr(g_e1);
    float*  esum   = (float*)sym_addr(g_esum);
    __half* ph     = (__half*)sym_addr(g_ph);
    __half* fusedh = (__half*)sym_addr(g_fusedh);
    float*  Wcomb  = (float*)sym_addr(g_Wcomb);
    int*    cntA   = (int*)sym_addr(g_cntA);
    int*    cntB   = (int*)sym_addr(g_cntB);
    int*    rpA    = (int*)sym_addr(g_rpA);
    int*    rpB    = (int*)sym_addr(g_rpB);
    int*    curA   = (int*)sym_addr(g_curA);
    int*    curB   = (int*)sym_addr(g_curB);
    Pair*   prsA   = (Pair*)sym_addr(g_pairsA);
    Pair*   prsB   = (Pair*)sym_addr(g_pairsB);

    size_t smem = (size_t)(2 * DD * MSTR) * sizeof(float);
    cudaFuncSetAttribute(gemm2_kernel<0>, cudaFuncAttributeMaxDynamicSharedMemorySize, (int)smem);
    cudaFuncSetAttribute(gemm2_kernel<1>, cudaFuncAttributeMaxDynamicSharedMemorySize, (int)smem);

    const int buildGrid = (2 * NNZ + 4 * 256 - 1) / (4 * 256);

    // CSR build (sub-bucketed counting sort)
    clear_kernel<<<2048, 256>>>(cntA, SUB * N_EDGE, cntB, SUB * N_POI);
    hist2_kernel<<<buildGrid, 256>>>(p2e_r, e2p_r, cntA, cntB);
    rowsum_kernel<<<512, 256>>>((const int4*)cntA, (const int4*)cntB, rpA, rpB);
    scan2_kernel<<<2, 1024>>>(rpA, N_EDGE, rpB, N_POI);
    cursor_kernel<<<512, 256>>>(rpA, (const int4*)cntA, (int4*)curA,
                                rpB, (const int4*)cntB, (int4*)curB);
    scatter2_kernel<<<buildGrid, 256>>>(p2e_r, p2e_c, p2e_v, curA, prsA,
                                        e2p_r, e2p_c, e2p_v, curB, prsB);

    wfold_kernel<<<DD, 256>>>(Wfus, Wpoi, Wedge, Wcomb);
    conv_kernel<<<2048, 256>>>((const float4*)poi, (uint2*)ph, N_POI * 32);

    const int gemmBlocks = (N_EDGE + GR - 1) / GR;

    // layer 1
    spmmA_kernel<<<(N_EDGE + 7) / 8, 256>>>(rpA, prsA, ph, msg);
    gemm2_kernel<0><<<gemmBlocks, 256, smem>>>(Wcomb, msg, edge, fusedh, e1, esum, nullptr);
    spmmB_kernel<0><<<(N_POI + 7) / 8, 256>>>(rpB, prsB, fusedh, poi, p1, ph, nullptr);

    // layer 2 (last)
    spmmA_kernel<<<(N_EDGE + 7) / 8, 256>>>(rpA, prsA, ph, msg);
    gemm2_kernel<1><<<gemmBlocks, 256, smem>>>(Wcomb, msg, e1, fusedh, nullptr, esum, out_edge);
    spmmB_kernel<1><<<(N_POI + 7) / 8, 256>>>(rpB, prsB, fusedh, poi, p1, nullptr, out);
}

// round 8
// speedup vs baseline: 2.2508x; 1.1235x over previous
#include <cuda_runtime.h>
#include <cuda_fp16.h>
#include <mma.h>

using namespace nvcuda;

#define N_POI  100000
#define N_EDGE 50000
#define NNZ    3200000
#define DD     128
#define SUB    8

#define SCAN_ELEMS 2048
#define NBLK_A ((N_EDGE + SCAN_ELEMS - 1) / SCAN_ELEMS)   // 25
#define NBLK_B ((N_POI  + SCAN_ELEMS - 1) / SCAN_ELEMS)   // 49

struct Pair { int c; float v; };

// ---------------- static scratch ----------------
__device__ float g_msg [(size_t)N_EDGE * DD];
__device__ float g_p1  [(size_t)N_POI * DD];
__device__ float g_e1  [(size_t)N_EDGE * DD];
__device__ float g_esum[(size_t)N_EDGE * DD];
__device__ __half g_ph    [(size_t)N_POI * DD];
__device__ __half g_fusedh[(size_t)N_EDGE * DD];
__device__ float g_Wcomb[DD * 256];

__device__ int  g_cntA[SUB * N_EDGE];
__device__ int  g_cntB[SUB * N_POI];
__device__ int  g_rpA [N_EDGE + 1];
__device__ int  g_rpB [N_POI + 1];
__device__ int  g_curA[SUB * N_EDGE];
__device__ int  g_curB[SUB * N_POI];
__device__ int  g_auxA[NBLK_A];
__device__ int  g_auxB[NBLK_B];
__device__ Pair g_pairsA[NNZ];
__device__ Pair g_pairsB[NNZ];

// ---------------- CSR build ----------------
__global__ void clear_kernel(int* __restrict__ a, int na, int* __restrict__ b, int nb) {
    for (int i = blockIdx.x * blockDim.x + threadIdx.x; i < na + nb; i += gridDim.x * blockDim.x) {
        if (i < na) a[i] = 0; else b[i - na] = 0;
    }
}

__global__ void __launch_bounds__(256) hist2_kernel(const int* __restrict__ rA, const int* __restrict__ rB,
                                                    int* __restrict__ cA, int* __restrict__ cB) {
    const int total = 2 * NNZ;
    const int S = gridDim.x * blockDim.x;
    int base = blockIdx.x * blockDim.x + threadIdx.x;
    int sub = base & (SUB - 1);
    for (; base < total; base += 4 * S) {
        int r[4]; bool m[4]; bool isA[4];
#pragma unroll
        for (int j = 0; j < 4; j++) {
            int i = base + j * S;
            m[j] = i < total;
            isA[j] = i < NNZ;
            if (m[j]) r[j] = isA[j] ? rA[i] : rB[i - NNZ];
        }
#pragma unroll
        for (int j = 0; j < 4; j++) {
            if (m[j]) {
                if (isA[j]) atomicAdd(&cA[r[j] * SUB + sub], 1);
                else        atomicAdd(&cB[r[j] * SUB + sub], 1);
            }
        }
    }
}

// row totals -> rp arrays (pre-scan)
__global__ void rowsum_kernel(const int4* __restrict__ cntA, const int4* __restrict__ cntB,
                              int* __restrict__ rpA, int* __restrict__ rpB) {
    const int total = N_EDGE + N_POI;
    for (int r = blockIdx.x * blockDim.x + threadIdx.x; r < total; r += gridDim.x * blockDim.x) {
        if (r < N_EDGE) {
            int4 a = cntA[r * 2], b = cntA[r * 2 + 1];
            rpA[r] = a.x + a.y + a.z + a.w + b.x + b.y + b.z + b.w;
        } else {
            int rr = r - N_EDGE;
            int4 a = cntB[rr * 2], b = cntB[rr * 2 + 1];
            rpB[rr] = a.x + a.y + a.z + a.w + b.x + b.y + b.z + b.w;
        }
    }
}

// Per-block exclusive scan of 2048 elements (1024 threads, 2 elems/thread).
// Blocks [0, NBLK_A) handle rpA, blocks [NBLK_A, NBLK_A+NBLK_B) handle rpB.
// Writes block total into aux.
__global__ void __launch_bounds__(1024) scan_blocks_kernel(int* __restrict__ dA, int* __restrict__ auxA,
                                                           int* __restrict__ dB, int* __restrict__ auxB) {
    __shared__ int sh[1024];
    int blk = blockIdx.x;
    int* data; int* aux; int n; int b;
    if (blk < NBLK_A) { data = dA; aux = auxA; n = N_EDGE; b = blk; }
    else              { data = dB; aux = auxB; n = N_POI;  b = blk - NBLK_A; }
    int t = threadIdx.x;
    int i0 = b * SCAN_ELEMS + t * 2;
    int x0 = (i0     < n) ? data[i0]     : 0;
    int x1 = (i0 + 1 < n) ? data[i0 + 1] : 0;
    int s = x0 + x1;
    sh[t] = s;
    __syncthreads();
#pragma unroll
    for (int off = 1; off < 1024; off <<= 1) {
        int v  = sh[t];
        int vo = (t >= off) ? sh[t - off] : 0;
        __syncthreads();
        sh[t] = v + vo;
        __syncthreads();
    }
    int excl = sh[t] - s;    // exclusive prefix of this thread's pair within block
    if (i0     < n) data[i0]     = excl;
    if (i0 + 1 < n) data[i0 + 1] = excl + x0;
    if (t == 1023) aux[b] = sh[1023];
}

// One block, 64 threads: warp 0 scans auxA (exclusive, in place) and writes rpA[N_EDGE];
// warp 1 scans auxB and writes rpB[N_POI].
__global__ void scan_aux_kernel(int* __restrict__ auxA, int* __restrict__ rpA,
                                int* __restrict__ auxB, int* __restrict__ rpB) {
    int w = threadIdx.x >> 5;
    int lane = threadIdx.x & 31;
    int* aux; int nblk; int* rpEnd;
    if (w == 0) { aux = auxA; nblk = NBLK_A; rpEnd = rpA + N_EDGE; }
    else        { aux = auxB; nblk = NBLK_B; rpEnd = rpB + N_POI; }
    int carry = 0;
    for (int c = 0; c < nblk; c += 32) {
        int idx = c + lane;
        int orig = (idx < nblk) ? aux[idx] : 0;
        int v = orig;
#pragma unroll
        for (int off = 1; off < 32; off <<= 1) {
            int tmp = __shfl_up_sync(0xFFFFFFFF, v, off);
            if (lane >= off) v += tmp;
        }
        if (idx < nblk) aux[idx] = v - orig + carry;
        carry += __shfl_sync(0xFFFFFFFF, v, 31);
    }
    if (lane == 0) *rpEnd = carry;
}

// cursors: base = within-block-scanned rp[r] + block offset; rp[r] <- absolute base;
// cur[r][s] = base + prefix of sub counts.
__global__ void cursor_kernel(int* __restrict__ rpA, const int* __restrict__ auxA,
                              const int4* __restrict__ cntA, int4* __restrict__ curA,
                              int* __restrict__ rpB, const int* __restrict__ auxB,
                              const int4* __restrict__ cntB, int4* __restrict__ curB) {
    const int total = N_EDGE + N_POI;
    for (int r = blockIdx.x * blockDim.x + threadIdx.x; r < total; r += gridDim.x * blockDim.x) {
        const int4* cnt; int4* cur; int base; int rr;
        if (r < N_EDGE) {
            rr = r; cnt = cntA; cur = curA;
            base = rpA[rr] + auxA[rr >> 11];
            rpA[rr] = base;
        } else {
            rr = r - N_EDGE; cnt = cntB; cur = curB;
            base = rpB[rr] + auxB[rr >> 11];
            rpB[rr] = base;
        }
        int4 a = cnt[rr * 2], b = cnt[rr * 2 + 1];
        int4 oa, ob;
        oa.x = base;
        oa.y = oa.x + a.x;
        oa.z = oa.y + a.y;
        oa.w = oa.z + a.z;
        ob.x = oa.w + a.w;
        ob.y = ob.x + b.x;
        ob.z = ob.y + b.y;
        ob.w = ob.z + b.z;
        cur[rr * 2] = oa;
        cur[rr * 2 + 1] = ob;
    }
}

__global__ void __launch_bounds__(256) scatter2_kernel(const int* __restrict__ rA, const int* __restrict__ cAi,
                                                       const float* __restrict__ vAi, int* __restrict__ curA,
                                                       Pair* __restrict__ pA,
                                                       const int* __restrict__ rB, const int* __restrict__ cBi,
                                                       const float* __restrict__ vBi, int* __restrict__ curB,
                                                       Pair* __restrict__ pB) {
    const int total = 2 * NNZ;
    const int S = gridDim.x * blockDim.x;
    int base = blockIdx.x * blockDim.x + threadIdx.x;
    int sub = base & (SUB - 1);
    for (; base < total; base += 4 * S) {
        int r[4], c[4]; float v[4]; bool m[4], isA[4];
#pragma unroll
        for (int j = 0; j < 4; j++) {
            int i = base + j * S;
            m[j] = i < total;
            isA[j] = i < NNZ;
            if (m[j]) {
                if (isA[j]) { r[j] = rA[i]; c[j] = cAi[i]; v[j] = vAi[i]; }
                else        { int k = i - NNZ; r[j] = rB[k]; c[j] = cBi[k]; v[j] = vBi[k]; }
            }
        }
#pragma unroll
        for (int j = 0; j < 4; j++) {
            if (m[j]) {
                Pair pr; pr.c = c[j]; pr.v = v[j];
                if (isA[j]) { int pos = atomicAdd(&curA[r[j] * SUB + sub], 1); pA[pos] = pr; }
                else        { int pos = atomicAdd(&curB[r[j] * SUB + sub], 1); pB[pos] = pr; }
            }
        }
    }
}

// ---------------- weight folding ----------------
__global__ void wfold_kernel(const float* __restrict__ Wfus, const float* __restrict__ Wpoi,
                             const float* __restrict__ Wedge, float* __restrict__ Wcomb) {
    __shared__ float row[256];
    int j = blockIdx.x;
    int t = threadIdx.x;
    row[t] = Wfus[j * 256 + t];
    __syncthreads();
    float s = 0.f;
    if (t < 128) {
#pragma unroll 8
        for (int m = 0; m < 128; m++) s += row[m] * Wpoi[m * 128 + t];
    } else {
        int tt = t - 128;
#pragma unroll 8
        for (int k = 0; k < 128; k++) s += row[128 + k] * Wedge[k * 128 + tt];
    }
    Wcomb[j * 256 + t] = s;
}

__global__ void conv_kernel(const float4* __restrict__ x, uint2* __restrict__ xh, int n4) {
    for (int i = blockIdx.x * blockDim.x + threadIdx.x; i < n4; i += gridDim.x * blockDim.x) {
        float4 v = x[i];
        __half2 h0 = __floats2half2_rn(v.x, v.y);
        __half2 h1 = __floats2half2_rn(v.z, v.w);
        uint2 u;
        u.x = *(unsigned*)&h0;
        u.y = *(unsigned*)&h1;
        xh[i] = u;
    }
}

// ---------------- SpMM core ----------------
__device__ __forceinline__ void spmm_row_acc_h(const Pair* __restrict__ prs,
                                               const uint2* __restrict__ xh,
                                               int s, int e, int lane,
                                               float& ax, float& ay, float& az, float& aw) {
    int j = s;
    for (; j + 4 <= e; j += 4) {
        Pair p0 = prs[j], p1 = prs[j + 1], p2 = prs[j + 2], p3 = prs[j + 3];
        uint2 g0 = xh[(size_t)p0.c * 32 + lane];
        uint2 g1 = xh[(size_t)p1.c * 32 + lane];
        uint2 g2 = xh[(size_t)p2.c * 32 + lane];
        uint2 g3 = xh[(size_t)p3.c * 32 + lane];
#pragma unroll
        for (int q = 0; q < 4; q++) {
            uint2 g = q == 0 ? g0 : q == 1 ? g1 : q == 2 ? g2 : g3;
            float v = q == 0 ? p0.v : q == 1 ? p1.v : q == 2 ? p2.v : p3.v;
            float2 f01 = __half22float2(*(__half2*)&g.x);
            float2 f23 = __half22float2(*(__half2*)&g.y);
            ax += v * f01.x; ay += v * f01.y; az += v * f23.x; aw += v * f23.y;
        }
    }
    for (; j < e; ++j) {
        Pair pp = prs[j];
        uint2 g = xh[(size_t)pp.c * 32 + lane];
        float2 f01 = __half22float2(*(__half2*)&g.x);
        float2 f23 = __half22float2(*(__half2*)&g.y);
        ax += pp.v * f01.x; ay += pp.v * f01.y; az += pp.v * f23.x; aw += pp.v * f23.y;
    }
}

__global__ void __launch_bounds__(256) spmmA_kernel(const int* __restrict__ rp,
                                                    const Pair* __restrict__ prs,
                                                    const __half* __restrict__ xh,
                                                    float* __restrict__ out) {
    int warp = (int)((blockIdx.x * (unsigned)blockDim.x + threadIdx.x) >> 5);
    if (warp >= N_EDGE) return;
    int lane = threadIdx.x & 31;
    int s = rp[warp], e = rp[warp + 1];
    float ax = 0.f, ay = 0.f, az = 0.f, aw = 0.f;
    spmm_row_acc_h(prs, (const uint2*)xh, s, e, lane, ax, ay, az, aw);
    ((float4*)out)[(size_t)warp * 32 + lane] = make_float4(ax, ay, az, aw);
}

template <int LAST>
__global__ void __launch_bounds__(256) spmmB_kernel(const int* __restrict__ rp,
                                                    const Pair* __restrict__ prs,
                                                    const __half* __restrict__ xh,
                                                    const float* __restrict__ poi,
                                                    float* __restrict__ p1,
                                                    __half* __restrict__ ph,
                                                    float* __restrict__ out) {
    int warp = (int)((blockIdx.x * (unsigned)blockDim.x + threadIdx.x) >> 5);
    if (warp >= N_POI) return;
    int lane = threadIdx.x & 31;
    int s = rp[warp], e = rp[warp + 1];
    float ax = 0.f, ay = 0.f, az = 0.f, aw = 0.f;
    spmm_row_acc_h(prs, (const uint2*)xh, s, e, lane, ax, ay, az, aw);
    size_t o = (size_t)warp * 32 + lane;
    float4 p0 = ((const float4*)poi)[o];
    if (LAST == 0) {
        float4 pn = make_float4(p0.x + ax, p0.y + ay, p0.z + az, p0.w + aw);
        ((float4*)p1)[o] = pn;
        __half2 h0 = __floats2half2_rn(pn.x, pn.y);
        __half2 h1 = __floats2half2_rn(pn.z, pn.w);
        uint2 u;
        u.x = *(unsigned*)&h0;
        u.y = *(unsigned*)&h1;
        ((uint2*)ph)[o] = u;
    } else {
        const float sc = 1.0f / 3.0f;
        float4 pv = ((const float4*)p1)[o];
        ((float4*)out)[o] = make_float4((p0.x + 2.f * pv.x + ax) * sc,
                                        (p0.y + 2.f * pv.y + ay) * sc,
                                        (p0.z + 2.f * pv.z + az) * sc,
                                        (p0.w + 2.f * pv.w + aw) * sc);
    }
}

// ---------------- edge GEMM (tf32 wmma) + residual epilogue ----------------
#define GR   128
#define MSTR 132

template <int LAST>
__global__ void __launch_bounds__(256, 1) gemm2_kernel(const float* __restrict__ Wcomb,
                                                       const float* __restrict__ msg,
                                                       const float* __restrict__ e_in,
                                                       __half* __restrict__ fused_h,
                                                       float* __restrict__ e_out,
                                                       float* __restrict__ esum,
                                                       float* __restrict__ out_edge) {
    extern __shared__ float sh[];
    float* Ws = sh;                 // [128 k][MSTR] transposed weights; reused as C buffer
    float* xs = sh + DD * MSTR;     // [128 r][MSTR] input rows
    int tid = threadIdx.x;
    int wid = tid >> 5;
    int row0 = blockIdx.x * GR;
    int warp_m = wid & 3;
    int warp_n = wid >> 2;

    wmma::fragment<wmma::accumulator, 16, 16, 8, float> acc[2][4];
#pragma unroll
    for (int m = 0; m < 2; m++)
#pragma unroll
        for (int n = 0; n < 4; n++) wmma::fill_fragment(acc[m][n], 0.f);

#pragma unroll
    for (int phase = 0; phase < 2; phase++) {
        const float* src = phase ? e_in : msg;
        int koff = phase * 128;
        if (phase) __syncthreads();
        for (int idx = tid; idx < DD * DD; idx += 256) {
            int j = idx >> 7, k = idx & 127;
            Ws[k * MSTR + j] = Wcomb[j * 256 + koff + k];
        }
        const float4* s4 = (const float4*)src;
        for (int idx = tid; idx < GR * 32; idx += 256) {
            int r = idx >> 5, k4 = idx & 31;
            int gr = row0 + r;
            float4 v = (gr < N_EDGE) ? s4[(size_t)gr * 32 + k4] : make_float4(0.f, 0.f, 0.f, 0.f);
            *(float4*)&xs[r * MSTR + k4 * 4] = v;
        }
        __syncthreads();

        for (int k0 = 0; k0 < DD; k0 += 8) {
            wmma::fragment<wmma::matrix_a, 16, 16, 8, wmma::precision::tf32, wmma::row_major> a[2];
#pragma unroll
            for (int m = 0; m < 2; m++) {
                wmma::load_matrix_sync(a[m], &xs[(warp_m * 32 + m * 16) * MSTR + k0], MSTR);
#pragma unroll
                for (int t = 0; t < a[m].num_elements; t++)
                    a[m].x[t] = wmma::__float_to_tf32(a[m].x[t]);
            }
#pragma unroll
            for (int n = 0; n < 4; n++) {
                wmma::fragment<wmma::matrix_b, 16, 16, 8, wmma::precision::tf32, wmma::row_major> b;
                wmma::load_matrix_sync(b, &Ws[k0 * MSTR + warp_n * 64 + n * 16], MSTR);
#pragma unroll
                for (int t = 0; t < b.num_elements; t++)
                    b.x[t] = wmma::__float_to_tf32(b.x[t]);
#pragma unroll
                for (int m = 0; m < 2; m++)
                    wmma::mma_sync(acc[m][n], a[m], b, acc[m][n]);
            }
        }
    }

    __syncthreads();
#pragma unroll
    for (int m = 0; m < 2; m++)
#pragma unroll
        for (int n = 0; n < 4; n++)
            wmma::store_matrix_sync(&Ws[(warp_m * 32 + m * 16) * MSTR + warp_n * 64 + n * 16],
                                    acc[m][n], MSTR, wmma::mem_row_major);
    __syncthreads();

    int tx = tid & 15, ty = tid >> 4;
#pragma unroll
    for (int i = 0; i < 8; i++) {
        int r = ty * 8 + i;
        int gr = row0 + r;
        if (gr >= N_EDGE) continue;
        size_t base = (size_t)gr * DD + tx * 8;
        float f[8];
#pragma unroll
        for (int j = 0; j < 8; j++) f[j] = Ws[r * MSTR + tx * 8 + j];
        __half2 h[4];
#pragma unroll
        for (int j = 0; j < 4; j++) h[j] = __floats2half2_rn(f[2 * j], f[2 * j + 1]);
        uint4 hv;
        hv.x = *(unsigned*)&h[0]; hv.y = *(unsigned*)&h[1];
        hv.z = *(unsigned*)&h[2]; hv.w = *(unsigned*)&h[3];
        ((uint4*)fused_h)[(size_t)gr * 16 + tx] = hv;

        float eo[8];
#pragma unroll
        for (int j = 0; j < 8; j++) eo[j] = xs[r * MSTR + tx * 8 + j];
        if (LAST == 0) {
            float en[8];
#pragma unroll
            for (int j = 0; j < 8; j++) en[j] = eo[j] + f[j];
            *(float4*)&e_out[base]     = make_float4(en[0], en[1], en[2], en[3]);
            *(float4*)&e_out[base + 4] = make_float4(en[4], en[5], en[6], en[7]);
            *(float4*)&esum[base]     = make_float4(eo[0] + en[0], eo[1] + en[1], eo[2] + en[2], eo[3] + en[3]);
            *(float4*)&esum[base + 4] = make_float4(eo[4] + en[4], eo[5] + en[5], eo[6] + en[6], eo[7] + en[7]);
        } else {
            const float sc = 1.0f / 3.0f;
            float4 s0 = *(const float4*)&esum[base];
            float4 s1 = *(const float4*)&esum[base + 4];
            *(float4*)&out_edge[base]     = make_float4((s0.x + eo[0] + f[0]) * sc, (s0.y + eo[1] + f[1]) * sc,
                                                        (s0.z + eo[2] + f[2]) * sc, (s0.w + eo[3] + f[3]) * sc);
            *(float4*)&out_edge[base + 4] = make_float4((s1.x + eo[4] + f[4]) * sc, (s1.y + eo[5] + f[5]) * sc,
                                                        (s1.z + eo[6] + f[6]) * sc, (s1.w + eo[7] + f[7]) * sc);
        }
    }
}

// ---------------- host ----------------
static void* sym_addr(const void* s) {
    void* p = nullptr;
    cudaGetSymbolAddress(&p, s);
    return p;
}

extern "C" void kernel_launch(void* const* d_in, const int* in_sizes, int n_in,
                              void* d_out, int out_size) {
    const float* poi    = (const float*)d_in[0];
    const float* edge   = (const float*)d_in[1];
    const float* Wpoi   = (const float*)d_in[2];
    const float* Wedge  = (const float*)d_in[3];
    const float* Wfus   = (const float*)d_in[4];
    const int*   p2e_r  = (const int*)d_in[5];
    const int*   p2e_c  = (const int*)d_in[6];
    const float* p2e_v  = (const float*)d_in[7];
    const int*   e2p_r  = (const int*)d_in[8];
    const int*   e2p_c  = (const int*)d_in[9];
    const float* e2p_v  = (const float*)d_in[10];
    float* out = (float*)d_out;
    float* out_edge = out + (size_t)N_POI * DD;

    float*  msg    = (float*)sym_addr(g_msg);
    float*  p1     = (float*)sym_addr(g_p1);
    float*  e1     = (float*)sym_addr(g_e1);
    float*  esum   = (float*)sym_addr(g_esum);
    __half* ph     = (__half*)sym_addr(g_ph);
    __half* fusedh = (__half*)sym_addr(g_fusedh);
    float*  Wcomb  = (float*)sym_addr(g_Wcomb);
    int*    cntA   = (int*)sym_addr(g_cntA);
    int*    cntB   = (int*)sym_addr(g_cntB);
    int*    rpA    = (int*)sym_addr(g_rpA);
    int*    rpB    = (int*)sym_addr(g_rpB);
    int*    curA   = (int*)sym_addr(g_curA);
    int*    curB   = (int*)sym_addr(g_curB);
    int*    auxA   = (int*)sym_addr(g_auxA);
    int*    auxB   = (int*)sym_addr(g_auxB);
    Pair*   prsA   = (Pair*)sym_addr(g_pairsA);
    Pair*   prsB   = (Pair*)sym_addr(g_pairsB);

    size_t smem = (size_t)(2 * DD * MSTR) * sizeof(float);
    cudaFuncSetAttribute(gemm2_kernel<0>, cudaFuncAttributeMaxDynamicSharedMemorySize, (int)smem);
    cudaFuncSetAttribute(gemm2_kernel<1>, cudaFuncAttributeMaxDynamicSharedMemorySize, (int)smem);

    const int buildGrid = (2 * NNZ + 4 * 256 - 1) / (4 * 256);

    // CSR build (sub-bucketed counting sort, hierarchical scan)
    clear_kernel<<<2048, 256>>>(cntA, SUB * N_EDGE, cntB, SUB * N_POI);
    hist2_kernel<<<buildGrid, 256>>>(p2e_r, e2p_r, cntA, cntB);
    rowsum_kernel<<<512, 256>>>((const int4*)cntA, (const int4*)cntB, rpA, rpB);
    scan_blocks_kernel<<<NBLK_A + NBLK_B, 1024>>>(rpA, auxA, rpB, auxB);
    scan_aux_kernel<<<1, 64>>>(auxA, rpA, auxB, rpB);
    cursor_kernel<<<512, 256>>>(rpA, auxA, (const int4*)cntA, (int4*)curA,
                                rpB, auxB, (const int4*)cntB, (int4*)curB);
    scatter2_kernel<<<buildGrid, 256>>>(p2e_r, p2e_c, p2e_v, curA, prsA,
                                        e2p_r, e2p_c, e2p_v, curB, prsB);

    wfold_kernel<<<DD, 256>>>(Wfus, Wpoi, Wedge, Wcomb);
    conv_kernel<<<2048, 256>>>((const float4*)poi, (uint2*)ph, N_POI * 32);

    const int gemmBlocks = (N_EDGE + GR - 1) / GR;

    // layer 1
    spmmA_kernel<<<(N_EDGE + 7) / 8, 256>>>(rpA, prsA, ph, msg);
    gemm2_kernel<0><<<gemmBlocks, 256, smem>>>(Wcomb, msg, edge, fusedh, e1, esum, nullptr);
    spmmB_kernel<0><<<(N_POI + 7) / 8, 256>>>(rpB, prsB, fusedh, poi, p1, ph, nullptr);

    // layer 2 (last)
    spmmA_kernel<<<(N_EDGE + 7) / 8, 256>>>(rpA, prsA, ph, msg);
    gemm2_kernel<1><<<gemmBlocks, 256, smem>>>(Wcomb, msg, e1, fusedh, nullptr, esum, out_edge);
    spmmB_kernel<1><<<(N_POI + 7) / 8, 256>>>(rpB, prsB, fusedh, poi, p1, nullptr, out);
}